// round 4
// baseline (speedup 1.0000x reference)
#include <cuda_runtime.h>
#include <stdint.h>
#include <math.h>

// Problem constants (fixed by the dataset)
#define NN      100000          // total entities
#define NTEXTC  90000           // text entities
#define NRELC   500
#define HIDD    1280            // 5 samples * 256 hidden
#define CDIM    2560            // Hh(1280) | Ht(1280)
#define W1SZ    267264          // 256*1044

// ---------------- device scratch (static: no allocations allowed) ----------------
__device__ float g_T[(size_t)NN * CDIM];     // node tables: [n][0:1280]=Hh, [1280:2560]=Ht  (~1.02 GB)
__device__ float g_W1[5 * W1SZ];             // sampled w1, [s][k][col] row-major (k*1044+col)
__device__ float g_B[256 * CDIM];            // B[j][c]  : e0-part weights
__device__ float g_BX[10 * CDIM];            // BX[j][c] : extra-feature weights
__device__ float g_BR[256 * HIDD];           // BR[j][cc]: relation-block weights
__device__ float g_Rproj[NRELC * HIDD];      // relation proj + qproj + b1 folded in
__device__ float g_qb[HIDD];                 // qproj + b1
__device__ float g_w2s[HIDD];                // sampled w2, [s*256+k]
__device__ float g_b2mean;
__device__ float g_b1s[5 * 256];
__device__ int   g_indeg[NN];
__device__ int   g_outdeg[NN];
// acc: [F1 | R1 | F2 | R2], each 2*NN floats
#define OFF_F1 0
#define OFF_R1 (2*NN)
#define OFF_F2 (4*NN)
#define OFF_R2 (6*NN)
__device__ float g_acc[8 * NN];
__device__ float g_X10[NN * 10];             // [topic0,topic1,f1a,f1b,f2a,f2b,r1a,r1b,r2a,r2b]
__device__ int   g_idflag;                   // 1 = ids are int64, 0 = int32

// ---------------- JAX threefry2x32 (bit-exact) ----------------
__device__ __forceinline__ void tf2x32(uint32_t k0, uint32_t k1, uint32_t c0, uint32_t c1,
                                       uint32_t& o0, uint32_t& o1) {
    uint32_t k2 = k0 ^ k1 ^ 0x1BD11BDAu;
    uint32_t x0 = c0 + k0, x1 = c1 + k1;
#define TFR(r) { x0 += x1; x1 = (x1 << (r)) | (x1 >> (32 - (r))); x1 ^= x0; }
    TFR(13) TFR(15) TFR(26) TFR(6)   x0 += k1; x1 += k2 + 1u;
    TFR(17) TFR(29) TFR(16) TFR(24)  x0 += k2; x1 += k0 + 2u;
    TFR(13) TFR(15) TFR(26) TFR(6)   x0 += k0; x1 += k1 + 3u;
    TFR(17) TFR(29) TFR(16) TFR(24)  x0 += k1; x1 += k2 + 4u;
    TFR(13) TFR(15) TFR(26) TFR(6)   x0 += k2; x1 += k0 + 5u;
#undef TFR
    o0 = x0; o1 = x1;
}

// MODERN JAX (jax_threefry_partitionable=True, default since 0.4.36):
//   fold_in(key, s) = threefry_2x32(key, (0, s))                      -> full pair
//   split(key, 4): key_j = threefry(key, (0, j))                      -> full pair (fold-like)
//   random_bits(key, 32, size): bits[i] = o0 ^ o1 of threefry(key, (hi(i), lo(i)))
//     (the 64-bit path packs (o0<<32)|o1; the <=32-bit path XOR-folds: bits1 ^ bits2)
__device__ __forceinline__ void sample_keys(int s, uint32_t sk[4][2]) {
    uint32_t f0, f1; tf2x32(0u, 42u, 0u, (uint32_t)s, f0, f1);   // key(42) -> fold_in(s)
#pragma unroll
    for (int j = 0; j < 4; j++)
        tf2x32(f0, f1, 0u, (uint32_t)j, sk[j][0], sk[j][1]);     // fold-like split
    // sk[0]=w1, sk[1]=b1, sk[2]=w2, sk[3]=b2 (order of normal() calls)
}

__device__ __forceinline__ uint32_t rbits32(const uint32_t k[2], uint32_t i) {
    uint32_t y0, y1; tf2x32(k[0], k[1], 0u, i, y0, y1);
    return y0 ^ y1;   // partitionable 32-bit path XOR-folds the two output words
}

// JAX: u = uniform(key, lo=nextafter(-1,0), hi=1); normal = sqrt(2)*erfinv(u)
__device__ __forceinline__ float normal_from_bits(uint32_t bits) {
    float f = __uint_as_float(0x3f800000u | (bits >> 9)) - 1.0f;   // [0,1)
    const float lo = -0.99999994f;                                 // (1.0 - lo) rounds to 2.0f
    float u = fmaxf(lo, fmaf(f, 2.0f, lo));
    return 1.41421356f * erfinvf(u);
}
__device__ __forceinline__ float softplus_f(float x) {
    return (x > 20.f) ? x : log1pf(expf(x));
}

// ---------------- misc kernels ----------------
__global__ void zero_kernel() {
    int i = blockIdx.x * blockDim.x + threadIdx.x;
    if (i < NN)      g_indeg[i] = 0;
    if (i < NN)      g_outdeg[i] = 0;
    for (int j = i; j < 8 * NN; j += gridDim.x * blockDim.x) g_acc[j] = 0.f;
}

__global__ void detect_kernel(const unsigned* __restrict__ ids) {
    // if ids are int64 (values < 2^31), every odd 32-bit word is 0
    int any = 0;
    for (int i = 0; i < 128; i++) any |= (ids[2 * i + 1] != 0u);
    g_idflag = any ? 0 : 1;
}

__device__ __forceinline__ long fetch_id(const void* p, int e) {
    if (g_idflag) return (long)((const long long*)p)[e];
    return (long)((const int*)p)[e];
}

// ---------------- weight sampling (partitionable threefry) ----------------
__global__ void sample_w1_kernel(const float* __restrict__ mu, const float* __restrict__ rho) {
    int gid = blockIdx.x * blockDim.x + threadIdx.x;
    if (gid >= 5 * W1SZ) return;
    int s = gid / W1SZ;
    int i = gid - s * W1SZ;
    uint32_t sk[4][2]; sample_keys(s, sk);
    float nz = normal_from_bits(rbits32(sk[0], (uint32_t)i));
    g_W1[gid] = mu[i] + nz * softplus_f(rho[i]);
}

__global__ void sample_small_kernel(const float* __restrict__ b1mu, const float* __restrict__ b1rho,
                                    const float* __restrict__ w2mu, const float* __restrict__ w2rho,
                                    const float* __restrict__ b2mu, const float* __restrict__ b2rho) {
    int gid = blockIdx.x * blockDim.x + threadIdx.x;
    if (gid < 5 * 256) {                       // b1
        int s = gid / 256, i = gid % 256;
        uint32_t sk[4][2]; sample_keys(s, sk);
        float nz = normal_from_bits(rbits32(sk[1], (uint32_t)i));
        g_b1s[s * 256 + i] = b1mu[i] + nz * softplus_f(b1rho[i]);
    } else if (gid < 10 * 256) {               // w2
        int g = gid - 5 * 256;
        int s = g / 256, i = g % 256;
        uint32_t sk[4][2]; sample_keys(s, sk);
        float nz = normal_from_bits(rbits32(sk[2], (uint32_t)i));
        g_w2s[s * 256 + i] = w2mu[i] + nz * softplus_f(w2rho[i]);
    } else if (gid == 10 * 256) {              // b2 (scalar), averaged over samples
        float sum = 0.f;
        for (int s = 0; s < 5; s++) {
            uint32_t sk[4][2]; sample_keys(s, sk);
            float nz = normal_from_bits(rbits32(sk[3], 0u));
            sum += b2mu[0] + nz * softplus_f(b2rho[0]);
        }
        g_b2mean = sum / 5.0f;
    }
}

// ---------------- DDE (segment-mean message passing, 2-dim features) ----------------
__global__ void scat1_kernel(const void* __restrict__ hid, const void* __restrict__ tidp,
                             const float* __restrict__ topic, int E) {
    int e = blockIdx.x * blockDim.x + threadIdx.x;
    if (e >= E) return;
    long h = fetch_id(hid, e), t = fetch_id(tidp, e);
    float2 th = *(const float2*)&topic[2 * h];
    float2 tt = *(const float2*)&topic[2 * t];
    atomicAdd(&g_acc[OFF_F1 + 2 * t],     th.x);
    atomicAdd(&g_acc[OFF_F1 + 2 * t + 1], th.y);
    atomicAdd(&g_acc[OFF_R1 + 2 * h],     tt.x);
    atomicAdd(&g_acc[OFF_R1 + 2 * h + 1], tt.y);
    atomicAdd(&g_indeg[t], 1);
    atomicAdd(&g_outdeg[h], 1);
}

__global__ void fin1_kernel(const float* __restrict__ topic) {
    int n = blockIdx.x * blockDim.x + threadIdx.x;
    if (n >= NN) return;
    float di = fmaxf((float)g_indeg[n], 1.f);
    float dd = fmaxf((float)g_outdeg[n], 1.f);
    float* x = &g_X10[n * 10];
    x[0] = topic[2 * n]; x[1] = topic[2 * n + 1];
    x[2] = g_acc[OFF_F1 + 2 * n] / di;  x[3] = g_acc[OFF_F1 + 2 * n + 1] / di;
    x[6] = g_acc[OFF_R1 + 2 * n] / dd;  x[7] = g_acc[OFF_R1 + 2 * n + 1] / dd;
}

__global__ void scat2_kernel(const void* __restrict__ hid, const void* __restrict__ tidp, int E) {
    int e = blockIdx.x * blockDim.x + threadIdx.x;
    if (e >= E) return;
    long h = fetch_id(hid, e), t = fetch_id(tidp, e);
    atomicAdd(&g_acc[OFF_F2 + 2 * t],     g_X10[h * 10 + 2]);
    atomicAdd(&g_acc[OFF_F2 + 2 * t + 1], g_X10[h * 10 + 3]);
    atomicAdd(&g_acc[OFF_R2 + 2 * h],     g_X10[t * 10 + 6]);
    atomicAdd(&g_acc[OFF_R2 + 2 * h + 1], g_X10[t * 10 + 7]);
}

__global__ void fin2_kernel() {
    int n = blockIdx.x * blockDim.x + threadIdx.x;
    if (n >= NN) return;
    float di = fmaxf((float)g_indeg[n], 1.f);
    float dd = fmaxf((float)g_outdeg[n], 1.f);
    float* x = &g_X10[n * 10];
    x[4] = g_acc[OFF_F2 + 2 * n] / di;  x[5] = g_acc[OFF_F2 + 2 * n + 1] / di;
    x[8] = g_acc[OFF_R2 + 2 * n] / dd;  x[9] = g_acc[OFF_R2 + 2 * n + 1] / dd;
}

// ---------------- weight-matrix prep ----------------
// triple cols: [q:0-255 | h_e[h]:256-521 | h_r:522-777 | h_e[t]:778-1043]
// h_e cols: [e0:0-255 | topic,f1,f2,r1,r2 : 256-265]
__global__ void prepB_kernel() {
    int gid = blockIdx.x * blockDim.x + threadIdx.x;
    if (gid < 256 * CDIM) {
        int j = gid / CDIM, c = gid % CDIM;
        int tbl = c / 1280, cc = c % 1280;
        int s = cc / 256, k = cc % 256;
        int basecol = tbl ? 778 : 256;
        g_B[j * CDIM + c] = g_W1[(size_t)s * W1SZ + k * 1044 + basecol + j];
    } else if (gid < 256 * CDIM + 10 * CDIM) {
        int idx = gid - 256 * CDIM;
        int j = idx / CDIM, c = idx % CDIM;
        int tbl = c / 1280, cc = c % 1280;
        int s = cc / 256, k = cc % 256;
        int basecol = tbl ? 1034 : 512;
        g_BX[j * CDIM + c] = g_W1[(size_t)s * W1SZ + k * 1044 + basecol + j];
    } else if (gid < 256 * CDIM + 10 * CDIM + 256 * HIDD) {
        int idx = gid - 256 * CDIM - 10 * CDIM;
        int j = idx / HIDD, cc = idx % HIDD;
        int s = cc / 256, k = cc % 256;
        g_BR[j * HIDD + cc] = g_W1[(size_t)s * W1SZ + k * 1044 + 522 + j];
    }
}

__global__ void qb_kernel(const float* __restrict__ q) {
    int cc = blockIdx.x * blockDim.x + threadIdx.x;
    if (cc >= HIDD) return;
    int s = cc / 256, k = cc % 256;
    const float* w = &g_W1[(size_t)s * W1SZ + k * 1044];
    float sum = 0.f;
    for (int j = 0; j < 256; j++) sum += q[j] * w[j];
    g_qb[cc] = sum + g_b1s[cc];
}

__global__ void rproj_kernel(const float* __restrict__ rel, int nrel) {
    int gid = blockIdx.x * blockDim.x + threadIdx.x;
    if (gid >= nrel * HIDD) return;
    int r = gid / HIDD, cc = gid % HIDD;
    const float* rr = &rel[r * 256];
    float sum = 0.f;
    for (int j = 0; j < 256; j++) sum += rr[j] * g_BR[j * HIDD + cc];
    g_Rproj[r * HIDD + cc] = sum + g_qb[cc];   // fold qproj+b1 here
}

// ---------------- main GEMM: T[n][c] = e0[n][0:256] @ B + X10[n][0:10] @ BX ----------------
__global__ void __launch_bounds__(256, 2)
gemm_kernel(const float* __restrict__ ent, const float* __restrict__ nontext,
            int ntext, int nnodes) {
    __shared__ __align__(16) float As[8][128];
    __shared__ __align__(16) float Bs[8][128];
    int tid = threadIdx.x;
    int m0 = blockIdx.y * 128;
    int n0 = blockIdx.x * 128;
    int arow = tid >> 1;
    int acol = (tid & 1) * 4;
    int brow = tid >> 5;
    int bcol = (tid & 31) * 4;
    int tx = tid & 15, ty = tid >> 4;

    float acc[8][8];
#pragma unroll
    for (int i = 0; i < 8; i++)
#pragma unroll
        for (int j = 0; j < 8; j++) acc[i][j] = 0.f;

    int gm = m0 + arow;
    const float* arowptr = nullptr;
    if (gm < nnodes) arowptr = (gm < ntext) ? ent + (size_t)gm * 256 : nontext;

    for (int k0 = 0; k0 < 256; k0 += 8) {
        float4 av = make_float4(0.f, 0.f, 0.f, 0.f);
        if (arowptr) av = *(const float4*)(arowptr + k0 + acol);
        float4 bv = *(const float4*)(g_B + (size_t)(k0 + brow) * CDIM + n0 + bcol);
        __syncthreads();
        As[acol + 0][arow] = av.x;
        As[acol + 1][arow] = av.y;
        As[acol + 2][arow] = av.z;
        As[acol + 3][arow] = av.w;
        *(float4*)&Bs[brow][bcol] = bv;
        __syncthreads();
#pragma unroll
        for (int kk = 0; kk < 8; kk++) {
            float4 a0 = *(const float4*)&As[kk][ty * 4];
            float4 a1 = *(const float4*)&As[kk][ty * 4 + 64];
            float4 b0 = *(const float4*)&Bs[kk][tx * 4];
            float4 b1 = *(const float4*)&Bs[kk][tx * 4 + 64];
            float avx[8] = {a0.x, a0.y, a0.z, a0.w, a1.x, a1.y, a1.z, a1.w};
            float bvx[8] = {b0.x, b0.y, b0.z, b0.w, b1.x, b1.y, b1.z, b1.w};
#pragma unroll
            for (int i = 0; i < 8; i++)
#pragma unroll
                for (int j = 0; j < 8; j++) acc[i][j] += avx[i] * bvx[j];
        }
    }

    // epilogue: add X10 @ BX
    int rbase[2] = {m0 + ty * 4, m0 + ty * 4 + 64};
    int cbase[2] = {n0 + tx * 4, n0 + tx * 4 + 64};
#pragma unroll
    for (int j = 0; j < 10; j++) {
        float bx[8];
#pragma unroll
        for (int jj = 0; jj < 8; jj++) bx[jj] = g_BX[j * CDIM + cbase[jj >> 2] + (jj & 3)];
#pragma unroll
        for (int i = 0; i < 8; i++) {
            int row = rbase[i >> 2] + (i & 3);
            float xv = (row < nnodes) ? g_X10[row * 10 + j] : 0.f;
#pragma unroll
            for (int jj = 0; jj < 8; jj++) acc[i][jj] += xv * bx[jj];
        }
    }
    // store
#pragma unroll
    for (int i = 0; i < 8; i++) {
        int row = rbase[i >> 2] + (i & 3);
        if (row < nnodes) {
            float* dst = g_T + (size_t)row * CDIM;
            *(float4*)(dst + cbase[0]) = make_float4(acc[i][0], acc[i][1], acc[i][2], acc[i][3]);
            *(float4*)(dst + cbase[1]) = make_float4(acc[i][4], acc[i][5], acc[i][6], acc[i][7]);
        }
    }
}

// ---------------- edge phase: out[e] = mean_s( relu(pre) . w2_s + b2_s ) ----------------
__global__ void __launch_bounds__(256)
edge_kernel(const void* __restrict__ hid, const void* __restrict__ rid,
            const void* __restrict__ tidp, float* __restrict__ out, int E) {
    __shared__ float sw2[HIDD];
    for (int i = threadIdx.x; i < HIDD; i += blockDim.x) sw2[i] = g_w2s[i];
    __syncthreads();
    int warp = threadIdx.x >> 5, lane = threadIdx.x & 31;
    int e = blockIdx.x * 8 + warp;
    if (e >= E) return;
    long h = fetch_id(hid, e);
    long t = fetch_id(tidp, e);
    long r = fetch_id(rid, e);
    const float4* ph = (const float4*)(g_T + (size_t)h * CDIM);
    const float4* pt = (const float4*)(g_T + (size_t)t * CDIM + 1280);
    const float4* pr = (const float4*)(g_Rproj + (size_t)r * HIDD);
    float acc = 0.f;
#pragma unroll
    for (int c = 0; c < 10; c++) {
        int idx = c * 32 + lane;
        float4 a = ph[idx];
        float4 b = pt[idx];
        float4 q = pr[idx];
        float4 w = *(const float4*)&sw2[idx * 4];
        acc += fmaxf(a.x + b.x + q.x, 0.f) * w.x;
        acc += fmaxf(a.y + b.y + q.y, 0.f) * w.y;
        acc += fmaxf(a.z + b.z + q.z, 0.f) * w.z;
        acc += fmaxf(a.w + b.w + q.w, 0.f) * w.w;
    }
#pragma unroll
    for (int o = 16; o; o >>= 1) acc += __shfl_xor_sync(0xFFFFFFFFu, acc, o);
    if (lane == 0) out[e] = acc * 0.2f + g_b2mean;
}

// ---------------- host ----------------
extern "C" void kernel_launch(void* const* d_in, const int* in_sizes, int n_in,
                              void* d_out, int out_size) {
    // input index base: the python-int scalar num_non_text_entities may or may not be
    // materialized as input 5 — detect via element count.
    int base = 0;
    if (n_in >= 17 && in_sizes[5] <= 16) base = 1;

    const void*  hid   = d_in[0];
    const void*  rid   = d_in[1];
    const void*  tidp  = d_in[2];
    const float* q     = (const float*)d_in[3];
    const float* ent   = (const float*)d_in[4];
    const float* rel   = (const float*)d_in[5 + base];
    const float* topic = (const float*)d_in[6 + base];
    const float* nont  = (const float*)d_in[7 + base];
    const float* w1mu  = (const float*)d_in[8 + base];
    const float* w1rho = (const float*)d_in[9 + base];
    const float* b1mu  = (const float*)d_in[10 + base];
    const float* b1rho = (const float*)d_in[11 + base];
    const float* w2mu  = (const float*)d_in[12 + base];
    const float* w2rho = (const float*)d_in[13 + base];
    const float* b2mu  = (const float*)d_in[14 + base];
    const float* b2rho = (const float*)d_in[15 + base];

    int E = in_sizes[0];
    int ntext = in_sizes[4] / 256;
    int nrel  = in_sizes[5 + base] / 256;
    int nnodes = NN;
    float* out = (float*)d_out;

    zero_kernel<<<(8 * NN + 255) / 256, 256>>>();
    detect_kernel<<<1, 1>>>((const unsigned*)hid);
    sample_w1_kernel<<<(5 * W1SZ + 255) / 256, 256>>>(w1mu, w1rho);
    sample_small_kernel<<<11, 256>>>(b1mu, b1rho, w2mu, w2rho, b2mu, b2rho);
    scat1_kernel<<<(E + 255) / 256, 256>>>(hid, tidp, topic, E);
    fin1_kernel<<<(NN + 255) / 256, 256>>>(topic);
    scat2_kernel<<<(E + 255) / 256, 256>>>(hid, tidp, E);
    fin2_kernel<<<(NN + 255) / 256, 256>>>();
    {
        int tot = 256 * CDIM + 10 * CDIM + 256 * HIDD;
        prepB_kernel<<<(tot + 255) / 256, 256>>>();
    }
    qb_kernel<<<(HIDD + 255) / 256, 256>>>(q);
    rproj_kernel<<<(nrel * HIDD + 255) / 256, 256>>>(rel, nrel);
    {
        dim3 grid(CDIM / 128, (nnodes + 127) / 128);
        gemm_kernel<<<grid, 256>>>(ent, nont, ntext, nnodes);
    }
    edge_kernel<<<(E + 7) / 8, 256>>>(hid, rid, tidp, out, E);
}

// round 5
// speedup vs baseline: 1.6501x; 1.6501x over previous
#include <cuda_runtime.h>
#include <stdint.h>
#include <math.h>

// Problem constants (fixed by the dataset)
#define NN      100000          // total entities
#define NTEXTC  90000           // text entities
#define NRELC   500
#define HIDD    1280            // 5 samples * 256 hidden
#define CDIM    2560            // Hh(1280) | Ht(1280)
#define W1SZ    267264          // 256*1044
#define KPAD    272             // 256 (e0) + 10 (X10) + 6 zero pad

// ---------------- device scratch (static: no allocations allowed) ----------------
__device__ float g_T[(size_t)NN * CDIM];     // node tables: [n][0:1280]=Hh, [1280:2560]=Ht  (~1.02 GB)
__device__ float g_W1[5 * W1SZ];             // sampled w1, [s][k][col] row-major (k*1044+col)
__device__ float g_Bc[KPAD * CDIM];          // combined [B(256) ; BX(10) ; 0(6)] x 2560
__device__ float g_BR[256 * HIDD];           // BR[j][cc]: relation-block weights
__device__ float g_Rproj[NRELC * HIDD];      // relation proj + qproj + b1 folded in
__device__ float g_qb[HIDD];                 // qproj + b1
__device__ float g_w2s[HIDD];                // sampled w2, [s*256+k]
__device__ float g_b2mean;
__device__ float g_b1s[5 * 256];
__device__ int   g_indeg[NN];
__device__ int   g_outdeg[NN];
// acc: [F1 | R1 | F2 | R2], each 2*NN floats
#define OFF_F1 0
#define OFF_R1 (2*NN)
#define OFF_F2 (4*NN)
#define OFF_R2 (6*NN)
__device__ float g_acc[8 * NN];
__device__ float g_X10[NN * 10];             // [topic0,topic1,f1a,f1b,f2a,f2b,r1a,r1b,r2a,r2b]
__device__ int   g_idflag;                   // 1 = ids are int64, 0 = int32

// ---------------- JAX threefry2x32 (bit-exact) ----------------
__device__ __forceinline__ void tf2x32(uint32_t k0, uint32_t k1, uint32_t c0, uint32_t c1,
                                       uint32_t& o0, uint32_t& o1) {
    uint32_t k2 = k0 ^ k1 ^ 0x1BD11BDAu;
    uint32_t x0 = c0 + k0, x1 = c1 + k1;
#define TFR(r) { x0 += x1; x1 = (x1 << (r)) | (x1 >> (32 - (r))); x1 ^= x0; }
    TFR(13) TFR(15) TFR(26) TFR(6)   x0 += k1; x1 += k2 + 1u;
    TFR(17) TFR(29) TFR(16) TFR(24)  x0 += k2; x1 += k0 + 2u;
    TFR(13) TFR(15) TFR(26) TFR(6)   x0 += k0; x1 += k1 + 3u;
    TFR(17) TFR(29) TFR(16) TFR(24)  x0 += k1; x1 += k2 + 4u;
    TFR(13) TFR(15) TFR(26) TFR(6)   x0 += k2; x1 += k0 + 5u;
#undef TFR
    o0 = x0; o1 = x1;
}

// MODERN JAX (jax_threefry_partitionable=True, default since 0.4.36):
//   fold_in(key, s) = threefry_2x32(key, (0, s))                      -> full pair
//   split(key, 4): key_j = threefry(key, (0, j))                      -> full pair (fold-like)
//   random_bits(key, 32, size): bits[i] = o0 ^ o1 of threefry(key, (hi(i), lo(i)))
__device__ __forceinline__ void sample_keys(int s, uint32_t sk[4][2]) {
    uint32_t f0, f1; tf2x32(0u, 42u, 0u, (uint32_t)s, f0, f1);   // key(42) -> fold_in(s)
#pragma unroll
    for (int j = 0; j < 4; j++)
        tf2x32(f0, f1, 0u, (uint32_t)j, sk[j][0], sk[j][1]);     // fold-like split
}

__device__ __forceinline__ uint32_t rbits32(const uint32_t k[2], uint32_t i) {
    uint32_t y0, y1; tf2x32(k[0], k[1], 0u, i, y0, y1);
    return y0 ^ y1;   // partitionable 32-bit path XOR-folds the two output words
}

// JAX: u = uniform(key, lo=nextafter(-1,0), hi=1); normal = sqrt(2)*erfinv(u)
__device__ __forceinline__ float normal_from_bits(uint32_t bits) {
    float f = __uint_as_float(0x3f800000u | (bits >> 9)) - 1.0f;   // [0,1)
    const float lo = -0.99999994f;
    float u = fmaxf(lo, fmaf(f, 2.0f, lo));
    return 1.41421356f * erfinvf(u);
}
__device__ __forceinline__ float softplus_f(float x) {
    return (x > 20.f) ? x : log1pf(expf(x));
}

// round-to-nearest fp32 -> tf32 (bit pattern in a b32 reg). RNA is load-bearing:
// truncation would introduce a systematic -2^-10 relative bias in the GEMM.
__device__ __forceinline__ uint32_t f2tf(float x) {
    uint32_t r; asm("cvt.rna.tf32.f32 %0, %1;" : "=r"(r) : "f"(x)); return r;
}

// ---------------- misc kernels ----------------
__global__ void zero_kernel() {
    int i = blockIdx.x * blockDim.x + threadIdx.x;
    if (i < NN)      g_indeg[i] = 0;
    if (i < NN)      g_outdeg[i] = 0;
    for (int j = i; j < 8 * NN; j += gridDim.x * blockDim.x) g_acc[j] = 0.f;
}

__global__ void detect_kernel(const unsigned* __restrict__ ids) {
    int any = 0;
    for (int i = 0; i < 128; i++) any |= (ids[2 * i + 1] != 0u);
    g_idflag = any ? 0 : 1;
}

__device__ __forceinline__ long fetch_id(const void* p, int e) {
    if (g_idflag) return (long)((const long long*)p)[e];
    return (long)((const int*)p)[e];
}

// ---------------- weight sampling (partitionable threefry) ----------------
__global__ void sample_w1_kernel(const float* __restrict__ mu, const float* __restrict__ rho) {
    int gid = blockIdx.x * blockDim.x + threadIdx.x;
    if (gid >= 5 * W1SZ) return;
    int s = gid / W1SZ;
    int i = gid - s * W1SZ;
    uint32_t sk[4][2]; sample_keys(s, sk);
    float nz = normal_from_bits(rbits32(sk[0], (uint32_t)i));
    g_W1[gid] = mu[i] + nz * softplus_f(rho[i]);
}

__global__ void sample_small_kernel(const float* __restrict__ b1mu, const float* __restrict__ b1rho,
                                    const float* __restrict__ w2mu, const float* __restrict__ w2rho,
                                    const float* __restrict__ b2mu, const float* __restrict__ b2rho) {
    int gid = blockIdx.x * blockDim.x + threadIdx.x;
    if (gid < 5 * 256) {                       // b1
        int s = gid / 256, i = gid % 256;
        uint32_t sk[4][2]; sample_keys(s, sk);
        float nz = normal_from_bits(rbits32(sk[1], (uint32_t)i));
        g_b1s[s * 256 + i] = b1mu[i] + nz * softplus_f(b1rho[i]);
    } else if (gid < 10 * 256) {               // w2
        int g = gid - 5 * 256;
        int s = g / 256, i = g % 256;
        uint32_t sk[4][2]; sample_keys(s, sk);
        float nz = normal_from_bits(rbits32(sk[2], (uint32_t)i));
        g_w2s[s * 256 + i] = w2mu[i] + nz * softplus_f(w2rho[i]);
    } else if (gid == 10 * 256) {              // b2 (scalar), averaged over samples
        float sum = 0.f;
        for (int s = 0; s < 5; s++) {
            uint32_t sk[4][2]; sample_keys(s, sk);
            float nz = normal_from_bits(rbits32(sk[3], 0u));
            sum += b2mu[0] + nz * softplus_f(b2rho[0]);
        }
        g_b2mean = sum / 5.0f;
    }
}

// ---------------- DDE (segment-mean message passing, 2-dim features) ----------------
__global__ void scat1_kernel(const void* __restrict__ hid, const void* __restrict__ tidp,
                             const float* __restrict__ topic, int E) {
    int e = blockIdx.x * blockDim.x + threadIdx.x;
    if (e >= E) return;
    long h = fetch_id(hid, e), t = fetch_id(tidp, e);
    float2 th = *(const float2*)&topic[2 * h];
    float2 tt = *(const float2*)&topic[2 * t];
    atomicAdd(&g_acc[OFF_F1 + 2 * t],     th.x);
    atomicAdd(&g_acc[OFF_F1 + 2 * t + 1], th.y);
    atomicAdd(&g_acc[OFF_R1 + 2 * h],     tt.x);
    atomicAdd(&g_acc[OFF_R1 + 2 * h + 1], tt.y);
    atomicAdd(&g_indeg[t], 1);
    atomicAdd(&g_outdeg[h], 1);
}

__global__ void fin1_kernel(const float* __restrict__ topic) {
    int n = blockIdx.x * blockDim.x + threadIdx.x;
    if (n >= NN) return;
    float di = fmaxf((float)g_indeg[n], 1.f);
    float dd = fmaxf((float)g_outdeg[n], 1.f);
    float* x = &g_X10[n * 10];
    x[0] = topic[2 * n]; x[1] = topic[2 * n + 1];
    x[2] = g_acc[OFF_F1 + 2 * n] / di;  x[3] = g_acc[OFF_F1 + 2 * n + 1] / di;
    x[6] = g_acc[OFF_R1 + 2 * n] / dd;  x[7] = g_acc[OFF_R1 + 2 * n + 1] / dd;
}

__global__ void scat2_kernel(const void* __restrict__ hid, const void* __restrict__ tidp, int E) {
    int e = blockIdx.x * blockDim.x + threadIdx.x;
    if (e >= E) return;
    long h = fetch_id(hid, e), t = fetch_id(tidp, e);
    atomicAdd(&g_acc[OFF_F2 + 2 * t],     g_X10[h * 10 + 2]);
    atomicAdd(&g_acc[OFF_F2 + 2 * t + 1], g_X10[h * 10 + 3]);
    atomicAdd(&g_acc[OFF_R2 + 2 * h],     g_X10[t * 10 + 6]);
    atomicAdd(&g_acc[OFF_R2 + 2 * h + 1], g_X10[t * 10 + 7]);
}

__global__ void fin2_kernel() {
    int n = blockIdx.x * blockDim.x + threadIdx.x;
    if (n >= NN) return;
    float di = fmaxf((float)g_indeg[n], 1.f);
    float dd = fmaxf((float)g_outdeg[n], 1.f);
    float* x = &g_X10[n * 10];
    x[4] = g_acc[OFF_F2 + 2 * n] / di;  x[5] = g_acc[OFF_F2 + 2 * n + 1] / di;
    x[8] = g_acc[OFF_R2 + 2 * n] / dd;  x[9] = g_acc[OFF_R2 + 2 * n + 1] / dd;
}

// ---------------- weight-matrix prep ----------------
// triple cols: [q:0-255 | h_e[h]:256-521 | h_r:522-777 | h_e[t]:778-1043]
// h_e cols: [e0:0-255 | topic,f1,f2,r1,r2 : 256-265]
// g_Bc row r (0..271), col c: tbl=c/1280 picks h(256)/t(778) base; rows 256..265 = X10 block; 266.. = 0
__global__ void prepB_kernel() {
    int gid = blockIdx.x * blockDim.x + threadIdx.x;
    if (gid < KPAD * CDIM) {
        int r = gid / CDIM, c = gid % CDIM;
        int tbl = c / 1280, cc = c % 1280;
        int s = cc / 256, k = cc % 256;
        int basecol = tbl ? 778 : 256;
        float v = 0.f;
        if (r < 266) v = g_W1[(size_t)s * W1SZ + k * 1044 + basecol + r];
        g_Bc[gid] = v;
    } else if (gid < KPAD * CDIM + 256 * HIDD) {
        int idx = gid - KPAD * CDIM;
        int j = idx / HIDD, cc = idx % HIDD;
        int s = cc / 256, k = cc % 256;
        g_BR[j * HIDD + cc] = g_W1[(size_t)s * W1SZ + k * 1044 + 522 + j];
    }
}

__global__ void qb_kernel(const float* __restrict__ q) {
    int cc = blockIdx.x * blockDim.x + threadIdx.x;
    if (cc >= HIDD) return;
    int s = cc / 256, k = cc % 256;
    const float* w = &g_W1[(size_t)s * W1SZ + k * 1044];
    float sum = 0.f;
    for (int j = 0; j < 256; j++) sum += q[j] * w[j];
    g_qb[cc] = sum + g_b1s[cc];
}

__global__ void rproj_kernel(const float* __restrict__ rel, int nrel) {
    int gid = blockIdx.x * blockDim.x + threadIdx.x;
    if (gid >= nrel * HIDD) return;
    int r = gid / HIDD, cc = gid % HIDD;
    const float* rr = &rel[r * 256];
    float sum = 0.f;
    for (int j = 0; j < 256; j++) sum += rr[j] * g_BR[j * HIDD + cc];
    g_Rproj[r * HIDD + cc] = sum + g_qb[cc];   // fold qproj+b1 here
}

// ---------------- main GEMM (tf32 tensor cores, fused X10 epilogue) ----------------
// T[100000, 2560] = Ax[100000, 272] @ g_Bc[272, 2560]
//   Ax = [e0(256) | X10(10) | 0(6)], tf32 inputs (RNA rounding), fp32 accumulate.
// 128x128 block tile, BK=16, 8 warps (2x4), warp tile 64x32 via m16n8k8 mma.
#define AS_STRIDE 17
#define BS_STRIDE 132

__device__ __forceinline__ void mma_tf32(float c[4], uint32_t a0, uint32_t a1, uint32_t a2, uint32_t a3,
                                         uint32_t b0, uint32_t b1) {
    asm volatile(
        "mma.sync.aligned.m16n8k8.row.col.f32.tf32.tf32.f32 "
        "{%0,%1,%2,%3}, {%4,%5,%6,%7}, {%8,%9}, {%0,%1,%2,%3};"
        : "+f"(c[0]), "+f"(c[1]), "+f"(c[2]), "+f"(c[3])
        : "r"(a0), "r"(a1), "r"(a2), "r"(a3), "r"(b0), "r"(b1));
}

__global__ void __launch_bounds__(256, 2)
gemm_tc_kernel(const float* __restrict__ ent, const float* __restrict__ nontext,
               int ntext, int nnodes) {
    __shared__ uint32_t As[2][128 * AS_STRIDE];   // [m][k] tf32 bits
    __shared__ uint32_t Bs[2][16 * BS_STRIDE];    // [k][n] tf32 bits

    const int tid  = threadIdx.x;
    const int lane = tid & 31;
    const int warp = tid >> 5;
    const int wm = warp >> 2;          // 0..1
    const int wn = warp & 3;           // 0..3
    const int g  = lane >> 2;          // groupID 0..7
    const int t4 = lane & 3;           // threadID_in_group 0..3
    const int m0 = blockIdx.y * 128;
    const int n0 = blockIdx.x * 128;

    float c[4][4][4];
#pragma unroll
    for (int mt = 0; mt < 4; mt++)
#pragma unroll
        for (int nt = 0; nt < 4; nt++)
#pragma unroll
            for (int i = 0; i < 4; i++) c[mt][nt][i] = 0.f;

    // global-load helper state for this thread's two A/B float4 slots
    // A: idx = tid + i*256 -> row = idx>>2 (0..127), k-col4 = (idx&3)*4
    // B: idx = tid + i*256 -> krow = idx>>5 (0..15), n-col4 = (idx&31)*4
    float4 aS[2], bS[2];

    auto load_tile = [&](int k0) {
#pragma unroll
        for (int i = 0; i < 2; i++) {
            int idx = tid + i * 256;
            // ---- A ----
            {
                int row = idx >> 2;
                int kc  = (idx & 3) * 4;
                int gm  = m0 + row;
                float4 v = make_float4(0.f, 0.f, 0.f, 0.f);
                if (gm < nnodes) {
                    const float* arow = (gm < ntext) ? ent + (size_t)gm * 256 : nontext;
                    int k = k0 + kc;
                    if (k + 3 < 256) {
                        v = *(const float4*)(arow + k);
                    } else {
                        const float* x10 = g_X10 + (size_t)gm * 10;
                        float vv[4];
#pragma unroll
                        for (int j = 0; j < 4; j++) {
                            int e = k + j;
                            vv[j] = (e < 256) ? arow[e] : ((e < 266) ? x10[e - 256] : 0.f);
                        }
                        v = make_float4(vv[0], vv[1], vv[2], vv[3]);
                    }
                }
                aS[i] = v;
            }
            // ---- B ----
            {
                int krow = idx >> 5;
                int nc   = (idx & 31) * 4;
                bS[i] = *(const float4*)(g_Bc + (size_t)(k0 + krow) * CDIM + n0 + nc);
            }
        }
    };

    auto store_tile = [&](int buf) {
        uint32_t* An = As[buf];
        uint32_t* Bn = Bs[buf];
#pragma unroll
        for (int i = 0; i < 2; i++) {
            int idx = tid + i * 256;
            {
                int row = idx >> 2;
                int kc  = (idx & 3) * 4;
                uint32_t* d = An + row * AS_STRIDE + kc;
                d[0] = f2tf(aS[i].x); d[1] = f2tf(aS[i].y);
                d[2] = f2tf(aS[i].z); d[3] = f2tf(aS[i].w);
            }
            {
                int krow = idx >> 5;
                int nc   = (idx & 31) * 4;
                uint32_t* d = Bn + krow * BS_STRIDE + nc;
                d[0] = f2tf(bS[i].x); d[1] = f2tf(bS[i].y);
                d[2] = f2tf(bS[i].z); d[3] = f2tf(bS[i].w);
            }
        }
    };

    // prologue: tile 0
    load_tile(0);
    store_tile(0);
    __syncthreads();

    const int NIT = KPAD / 16;   // 17
    for (int it = 0; it < NIT; it++) {
        int buf = it & 1;
        if (it + 1 < NIT) load_tile((it + 1) * 16);

        const uint32_t* A_ = As[buf];
        const uint32_t* B_ = Bs[buf];
#pragma unroll
        for (int kk = 0; kk < 2; kk++) {
            int k8 = kk * 8;
            uint32_t af[4][4];
#pragma unroll
            for (int mt = 0; mt < 4; mt++) {
                int r0 = wm * 64 + mt * 16 + g;
                af[mt][0] = A_[r0 * AS_STRIDE + k8 + t4];
                af[mt][1] = A_[(r0 + 8) * AS_STRIDE + k8 + t4];
                af[mt][2] = A_[r0 * AS_STRIDE + k8 + t4 + 4];
                af[mt][3] = A_[(r0 + 8) * AS_STRIDE + k8 + t4 + 4];
            }
            uint32_t bf[4][2];
#pragma unroll
            for (int nt = 0; nt < 4; nt++) {
                int nb = wn * 32 + nt * 8 + g;
                bf[nt][0] = B_[(k8 + t4) * BS_STRIDE + nb];
                bf[nt][1] = B_[(k8 + t4 + 4) * BS_STRIDE + nb];
            }
#pragma unroll
            for (int mt = 0; mt < 4; mt++)
#pragma unroll
                for (int nt = 0; nt < 4; nt++)
                    mma_tf32(c[mt][nt], af[mt][0], af[mt][1], af[mt][2], af[mt][3],
                             bf[nt][0], bf[nt][1]);
        }

        if (it + 1 < NIT) store_tile(buf ^ 1);
        __syncthreads();
    }

    // store C (fp32) to g_T
#pragma unroll
    for (int mt = 0; mt < 4; mt++) {
        int r0 = m0 + wm * 64 + mt * 16 + g;
        int r1 = r0 + 8;
#pragma unroll
        for (int nt = 0; nt < 4; nt++) {
            int cb = n0 + wn * 32 + nt * 8 + 2 * t4;
            if (r0 < nnodes)
                *(float2*)(g_T + (size_t)r0 * CDIM + cb) = make_float2(c[mt][nt][0], c[mt][nt][1]);
            if (r1 < nnodes)
                *(float2*)(g_T + (size_t)r1 * CDIM + cb) = make_float2(c[mt][nt][2], c[mt][nt][3]);
        }
    }
}

// ---------------- edge phase: out[e] = mean_s( relu(pre) . w2_s + b2_s ) ----------------
__global__ void __launch_bounds__(256)
edge_kernel(const void* __restrict__ hid, const void* __restrict__ rid,
            const void* __restrict__ tidp, float* __restrict__ out, int E) {
    __shared__ float sw2[HIDD];
    for (int i = threadIdx.x; i < HIDD; i += blockDim.x) sw2[i] = g_w2s[i];
    __syncthreads();
    int warp = threadIdx.x >> 5, lane = threadIdx.x & 31;
    int e = blockIdx.x * 8 + warp;
    if (e >= E) return;
    long h = fetch_id(hid, e);
    long t = fetch_id(tidp, e);
    long r = fetch_id(rid, e);
    const float4* ph = (const float4*)(g_T + (size_t)h * CDIM);
    const float4* pt = (const float4*)(g_T + (size_t)t * CDIM + 1280);
    const float4* pr = (const float4*)(g_Rproj + (size_t)r * HIDD);
    float acc = 0.f;
#pragma unroll
    for (int c = 0; c < 10; c++) {
        int idx = c * 32 + lane;
        float4 a = ph[idx];
        float4 b = pt[idx];
        float4 q = pr[idx];
        float4 w = *(const float4*)&sw2[idx * 4];
        acc += fmaxf(a.x + b.x + q.x, 0.f) * w.x;
        acc += fmaxf(a.y + b.y + q.y, 0.f) * w.y;
        acc += fmaxf(a.z + b.z + q.z, 0.f) * w.z;
        acc += fmaxf(a.w + b.w + q.w, 0.f) * w.w;
    }
#pragma unroll
    for (int o = 16; o; o >>= 1) acc += __shfl_xor_sync(0xFFFFFFFFu, acc, o);
    if (lane == 0) out[e] = acc * 0.2f + g_b2mean;
}

// ---------------- host ----------------
extern "C" void kernel_launch(void* const* d_in, const int* in_sizes, int n_in,
                              void* d_out, int out_size) {
    int base = 0;
    if (n_in >= 17 && in_sizes[5] <= 16) base = 1;

    const void*  hid   = d_in[0];
    const void*  rid   = d_in[1];
    const void*  tidp  = d_in[2];
    const float* q     = (const float*)d_in[3];
    const float* ent   = (const float*)d_in[4];
    const float* rel   = (const float*)d_in[5 + base];
    const float* topic = (const float*)d_in[6 + base];
    const float* nont  = (const float*)d_in[7 + base];
    const float* w1mu  = (const float*)d_in[8 + base];
    const float* w1rho = (const float*)d_in[9 + base];
    const float* b1mu  = (const float*)d_in[10 + base];
    const float* b1rho = (const float*)d_in[11 + base];
    const float* w2mu  = (const float*)d_in[12 + base];
    const float* w2rho = (const float*)d_in[13 + base];
    const float* b2mu  = (const float*)d_in[14 + base];
    const float* b2rho = (const float*)d_in[15 + base];

    int E = in_sizes[0];
    int ntext = in_sizes[4] / 256;
    int nrel  = in_sizes[5 + base] / 256;
    int nnodes = NN;
    float* out = (float*)d_out;

    zero_kernel<<<(8 * NN + 255) / 256, 256>>>();
    detect_kernel<<<1, 1>>>((const unsigned*)hid);
    sample_w1_kernel<<<(5 * W1SZ + 255) / 256, 256>>>(w1mu, w1rho);
    sample_small_kernel<<<11, 256>>>(b1mu, b1rho, w2mu, w2rho, b2mu, b2rho);
    scat1_kernel<<<(E + 255) / 256, 256>>>(hid, tidp, topic, E);
    fin1_kernel<<<(NN + 255) / 256, 256>>>(topic);
    scat2_kernel<<<(E + 255) / 256, 256>>>(hid, tidp, E);
    fin2_kernel<<<(NN + 255) / 256, 256>>>();
    {
        int tot = KPAD * CDIM + 256 * HIDD;
        prepB_kernel<<<(tot + 255) / 256, 256>>>();
    }
    qb_kernel<<<(HIDD + 255) / 256, 256>>>(q);
    rproj_kernel<<<(nrel * HIDD + 255) / 256, 256>>>(rel, nrel);
    {
        dim3 grid(CDIM / 128, (nnodes + 127) / 128);   // x = n-tiles (20), y = m-tiles (782)
        gemm_tc_kernel<<<grid, 256>>>(ent, nont, ntext, nnodes);
    }
    edge_kernel<<<(E + 7) / 8, 256>>>(hid, rid, tidp, out, E);
}

// round 6
// speedup vs baseline: 1.9100x; 1.1575x over previous
#include <cuda_runtime.h>
#include <cuda_fp16.h>
#include <stdint.h>
#include <math.h>

// Problem constants (fixed by the dataset)
#define NN      100000          // total entities
#define NTEXTC  90000           // text entities
#define NRELC   500
#define HIDD    1280            // 5 samples * 256 hidden
#define CDIM    2560            // Hh(1280) | Ht(1280)
#define W1SZ    267264          // 256*1044
#define KPAD    272             // 256 (e0) + 10 (X10) + 6 zero pad

// ---------------- device scratch (static: no allocations allowed) ----------------
__device__ __half g_Th[(size_t)NN * CDIM];   // node tables (fp16): [n][0:1280]=Hh, [1280:2560]=Ht (~512 MB)
__device__ float g_W1[5 * W1SZ];             // sampled w1, [s][k][col] row-major (k*1044+col)
__device__ float g_Bc[KPAD * CDIM];          // combined [B(256) ; BX(10) ; 0(6)] x 2560
__device__ float g_BR[256 * HIDD];           // BR[j][cc]: relation-block weights
__device__ __half g_Rp[NRELC * HIDD];        // relation proj + qproj + b1 folded in (fp16)
__device__ float g_qb[HIDD];                 // qproj + b1
__device__ float g_w2s[HIDD];                // sampled w2, [s*256+k]
__device__ float g_b2mean;
__device__ float g_b1s[5 * 256];
__device__ int   g_indeg[NN];
__device__ int   g_outdeg[NN];
// acc: [F1 | R1 | F2 | R2], each 2*NN floats
#define OFF_F1 0
#define OFF_R1 (2*NN)
#define OFF_F2 (4*NN)
#define OFF_R2 (6*NN)
__device__ float g_acc[8 * NN];
__device__ float g_X10[NN * 10];             // [topic0,topic1,f1a,f1b,f2a,f2b,r1a,r1b,r2a,r2b]
__device__ int   g_idflag;                   // 1 = ids are int64, 0 = int32

// ---------------- JAX threefry2x32 (bit-exact) ----------------
__device__ __forceinline__ void tf2x32(uint32_t k0, uint32_t k1, uint32_t c0, uint32_t c1,
                                       uint32_t& o0, uint32_t& o1) {
    uint32_t k2 = k0 ^ k1 ^ 0x1BD11BDAu;
    uint32_t x0 = c0 + k0, x1 = c1 + k1;
#define TFR(r) { x0 += x1; x1 = (x1 << (r)) | (x1 >> (32 - (r))); x1 ^= x0; }
    TFR(13) TFR(15) TFR(26) TFR(6)   x0 += k1; x1 += k2 + 1u;
    TFR(17) TFR(29) TFR(16) TFR(24)  x0 += k2; x1 += k0 + 2u;
    TFR(13) TFR(15) TFR(26) TFR(6)   x0 += k0; x1 += k1 + 3u;
    TFR(17) TFR(29) TFR(16) TFR(24)  x0 += k1; x1 += k2 + 4u;
    TFR(13) TFR(15) TFR(26) TFR(6)   x0 += k2; x1 += k0 + 5u;
#undef TFR
    o0 = x0; o1 = x1;
}

// MODERN JAX (jax_threefry_partitionable=True, default since 0.4.36):
//   fold_in(key, s) = threefry_2x32(key, (0, s))                      -> full pair
//   split(key, 4): key_j = threefry(key, (0, j))                      -> full pair (fold-like)
//   random_bits(key, 32, size): bits[i] = o0 ^ o1 of threefry(key, (hi(i), lo(i)))
__device__ __forceinline__ void sample_keys(int s, uint32_t sk[4][2]) {
    uint32_t f0, f1; tf2x32(0u, 42u, 0u, (uint32_t)s, f0, f1);   // key(42) -> fold_in(s)
#pragma unroll
    for (int j = 0; j < 4; j++)
        tf2x32(f0, f1, 0u, (uint32_t)j, sk[j][0], sk[j][1]);     // fold-like split
}

__device__ __forceinline__ uint32_t rbits32(const uint32_t k[2], uint32_t i) {
    uint32_t y0, y1; tf2x32(k[0], k[1], 0u, i, y0, y1);
    return y0 ^ y1;   // partitionable 32-bit path XOR-folds the two output words
}

// JAX: u = uniform(key, lo=nextafter(-1,0), hi=1); normal = sqrt(2)*erfinv(u)
__device__ __forceinline__ float normal_from_bits(uint32_t bits) {
    float f = __uint_as_float(0x3f800000u | (bits >> 9)) - 1.0f;   // [0,1)
    const float lo = -0.99999994f;
    float u = fmaxf(lo, fmaf(f, 2.0f, lo));
    return 1.41421356f * erfinvf(u);
}
__device__ __forceinline__ float softplus_f(float x) {
    return (x > 20.f) ? x : log1pf(expf(x));
}

// round-to-nearest fp32 -> tf32 (bit pattern in a b32 reg). RNA is load-bearing:
// truncation would introduce a systematic -2^-10 relative bias in the GEMM.
__device__ __forceinline__ uint32_t f2tf(float x) {
    uint32_t r; asm("cvt.rna.tf32.f32 %0, %1;" : "=r"(r) : "f"(x)); return r;
}

// ---------------- misc kernels ----------------
__global__ void zero_kernel() {
    int i = blockIdx.x * blockDim.x + threadIdx.x;
    if (i < NN)      g_indeg[i] = 0;
    if (i < NN)      g_outdeg[i] = 0;
    for (int j = i; j < 8 * NN; j += gridDim.x * blockDim.x) g_acc[j] = 0.f;
}

__global__ void detect_kernel(const unsigned* __restrict__ ids) {
    int any = 0;
    for (int i = 0; i < 128; i++) any |= (ids[2 * i + 1] != 0u);
    g_idflag = any ? 0 : 1;
}

__device__ __forceinline__ long fetch_id(const void* p, int e) {
    if (g_idflag) return (long)((const long long*)p)[e];
    return (long)((const int*)p)[e];
}

// ---------------- weight sampling (partitionable threefry) ----------------
__global__ void sample_w1_kernel(const float* __restrict__ mu, const float* __restrict__ rho) {
    int gid = blockIdx.x * blockDim.x + threadIdx.x;
    if (gid >= 5 * W1SZ) return;
    int s = gid / W1SZ;
    int i = gid - s * W1SZ;
    uint32_t sk[4][2]; sample_keys(s, sk);
    float nz = normal_from_bits(rbits32(sk[0], (uint32_t)i));
    g_W1[gid] = mu[i] + nz * softplus_f(rho[i]);
}

__global__ void sample_small_kernel(const float* __restrict__ b1mu, const float* __restrict__ b1rho,
                                    const float* __restrict__ w2mu, const float* __restrict__ w2rho,
                                    const float* __restrict__ b2mu, const float* __restrict__ b2rho) {
    int gid = blockIdx.x * blockDim.x + threadIdx.x;
    if (gid < 5 * 256) {                       // b1
        int s = gid / 256, i = gid % 256;
        uint32_t sk[4][2]; sample_keys(s, sk);
        float nz = normal_from_bits(rbits32(sk[1], (uint32_t)i));
        g_b1s[s * 256 + i] = b1mu[i] + nz * softplus_f(b1rho[i]);
    } else if (gid < 10 * 256) {               // w2
        int g = gid - 5 * 256;
        int s = g / 256, i = g % 256;
        uint32_t sk[4][2]; sample_keys(s, sk);
        float nz = normal_from_bits(rbits32(sk[2], (uint32_t)i));
        g_w2s[s * 256 + i] = w2mu[i] + nz * softplus_f(w2rho[i]);
    } else if (gid == 10 * 256) {              // b2 (scalar), averaged over samples
        float sum = 0.f;
        for (int s = 0; s < 5; s++) {
            uint32_t sk[4][2]; sample_keys(s, sk);
            float nz = normal_from_bits(rbits32(sk[3], 0u));
            sum += b2mu[0] + nz * softplus_f(b2rho[0]);
        }
        g_b2mean = sum / 5.0f;
    }
}

// ---------------- DDE (segment-mean message passing, 2-dim features) ----------------
__global__ void scat1_kernel(const void* __restrict__ hid, const void* __restrict__ tidp,
                             const float* __restrict__ topic, int E) {
    int e = blockIdx.x * blockDim.x + threadIdx.x;
    if (e >= E) return;
    long h = fetch_id(hid, e), t = fetch_id(tidp, e);
    float2 th = *(const float2*)&topic[2 * h];
    float2 tt = *(const float2*)&topic[2 * t];
    atomicAdd(&g_acc[OFF_F1 + 2 * t],     th.x);
    atomicAdd(&g_acc[OFF_F1 + 2 * t + 1], th.y);
    atomicAdd(&g_acc[OFF_R1 + 2 * h],     tt.x);
    atomicAdd(&g_acc[OFF_R1 + 2 * h + 1], tt.y);
    atomicAdd(&g_indeg[t], 1);
    atomicAdd(&g_outdeg[h], 1);
}

__global__ void fin1_kernel(const float* __restrict__ topic) {
    int n = blockIdx.x * blockDim.x + threadIdx.x;
    if (n >= NN) return;
    float di = fmaxf((float)g_indeg[n], 1.f);
    float dd = fmaxf((float)g_outdeg[n], 1.f);
    float* x = &g_X10[n * 10];
    x[0] = topic[2 * n]; x[1] = topic[2 * n + 1];
    x[2] = g_acc[OFF_F1 + 2 * n] / di;  x[3] = g_acc[OFF_F1 + 2 * n + 1] / di;
    x[6] = g_acc[OFF_R1 + 2 * n] / dd;  x[7] = g_acc[OFF_R1 + 2 * n + 1] / dd;
}

__global__ void scat2_kernel(const void* __restrict__ hid, const void* __restrict__ tidp, int E) {
    int e = blockIdx.x * blockDim.x + threadIdx.x;
    if (e >= E) return;
    long h = fetch_id(hid, e), t = fetch_id(tidp, e);
    atomicAdd(&g_acc[OFF_F2 + 2 * t],     g_X10[h * 10 + 2]);
    atomicAdd(&g_acc[OFF_F2 + 2 * t + 1], g_X10[h * 10 + 3]);
    atomicAdd(&g_acc[OFF_R2 + 2 * h],     g_X10[t * 10 + 6]);
    atomicAdd(&g_acc[OFF_R2 + 2 * h + 1], g_X10[t * 10 + 7]);
}

__global__ void fin2_kernel() {
    int n = blockIdx.x * blockDim.x + threadIdx.x;
    if (n >= NN) return;
    float di = fmaxf((float)g_indeg[n], 1.f);
    float dd = fmaxf((float)g_outdeg[n], 1.f);
    float* x = &g_X10[n * 10];
    x[4] = g_acc[OFF_F2 + 2 * n] / di;  x[5] = g_acc[OFF_F2 + 2 * n + 1] / di;
    x[8] = g_acc[OFF_R2 + 2 * n] / dd;  x[9] = g_acc[OFF_R2 + 2 * n + 1] / dd;
}

// ---------------- weight-matrix prep ----------------
// triple cols: [q:0-255 | h_e[h]:256-521 | h_r:522-777 | h_e[t]:778-1043]
// h_e cols: [e0:0-255 | topic,f1,f2,r1,r2 : 256-265]
// g_Bc row r (0..271), col c: tbl=c/1280 picks h(256)/t(778) base; rows 256..265 = X10 block; 266.. = 0
__global__ void prepB_kernel() {
    int gid = blockIdx.x * blockDim.x + threadIdx.x;
    if (gid < KPAD * CDIM) {
        int r = gid / CDIM, c = gid % CDIM;
        int tbl = c / 1280, cc = c % 1280;
        int s = cc / 256, k = cc % 256;
        int basecol = tbl ? 778 : 256;
        float v = 0.f;
        if (r < 266) v = g_W1[(size_t)s * W1SZ + k * 1044 + basecol + r];
        g_Bc[gid] = v;
    } else if (gid < KPAD * CDIM + 256 * HIDD) {
        int idx = gid - KPAD * CDIM;
        int j = idx / HIDD, cc = idx % HIDD;
        int s = cc / 256, k = cc % 256;
        g_BR[j * HIDD + cc] = g_W1[(size_t)s * W1SZ + k * 1044 + 522 + j];
    }
}

__global__ void qb_kernel(const float* __restrict__ q) {
    int cc = blockIdx.x * blockDim.x + threadIdx.x;
    if (cc >= HIDD) return;
    int s = cc / 256, k = cc % 256;
    const float* w = &g_W1[(size_t)s * W1SZ + k * 1044];
    float sum = 0.f;
    for (int j = 0; j < 256; j++) sum += q[j] * w[j];
    g_qb[cc] = sum + g_b1s[cc];
}

__global__ void rproj_kernel(const float* __restrict__ rel, int nrel) {
    int gid = blockIdx.x * blockDim.x + threadIdx.x;
    if (gid >= nrel * HIDD) return;
    int r = gid / HIDD, cc = gid % HIDD;
    const float* rr = &rel[r * 256];
    float sum = 0.f;
    for (int j = 0; j < 256; j++) sum += rr[j] * g_BR[j * HIDD + cc];
    g_Rp[r * HIDD + cc] = __float2half_rn(sum + g_qb[cc]);   // fold qproj+b1 here (fp16 store)
}

// ---------------- main GEMM (tf32 tensor cores, fused X10 epilogue, fp16 output) ----------------
// T[100000, 2560] = Ax[100000, 272] @ g_Bc[272, 2560]
//   Ax = [e0(256) | X10(10) | 0(6)], tf32 inputs (RNA rounding), fp32 accumulate, fp16 store.
// 128x128 block tile, BK=16, 8 warps (2x4), warp tile 64x32 via m16n8k8 mma.
#define AS_STRIDE 17
#define BS_STRIDE 132

__device__ __forceinline__ void mma_tf32(float c[4], uint32_t a0, uint32_t a1, uint32_t a2, uint32_t a3,
                                         uint32_t b0, uint32_t b1) {
    asm volatile(
        "mma.sync.aligned.m16n8k8.row.col.f32.tf32.tf32.f32 "
        "{%0,%1,%2,%3}, {%4,%5,%6,%7}, {%8,%9}, {%0,%1,%2,%3};"
        : "+f"(c[0]), "+f"(c[1]), "+f"(c[2]), "+f"(c[3])
        : "r"(a0), "r"(a1), "r"(a2), "r"(a3), "r"(b0), "r"(b1));
}

__global__ void __launch_bounds__(256, 2)
gemm_tc_kernel(const float* __restrict__ ent, const float* __restrict__ nontext,
               int ntext, int nnodes) {
    __shared__ uint32_t As[2][128 * AS_STRIDE];   // [m][k] tf32 bits
    __shared__ uint32_t Bs[2][16 * BS_STRIDE];    // [k][n] tf32 bits

    const int tid  = threadIdx.x;
    const int lane = tid & 31;
    const int warp = tid >> 5;
    const int wm = warp >> 2;          // 0..1
    const int wn = warp & 3;           // 0..3
    const int g  = lane >> 2;          // groupID 0..7
    const int t4 = lane & 3;           // threadID_in_group 0..3
    const int m0 = blockIdx.y * 128;
    const int n0 = blockIdx.x * 128;

    float c[4][4][4];
#pragma unroll
    for (int mt = 0; mt < 4; mt++)
#pragma unroll
        for (int nt = 0; nt < 4; nt++)
#pragma unroll
            for (int i = 0; i < 4; i++) c[mt][nt][i] = 0.f;

    float4 aS[2], bS[2];

    auto load_tile = [&](int k0) {
#pragma unroll
        for (int i = 0; i < 2; i++) {
            int idx = tid + i * 256;
            // ---- A ----
            {
                int row = idx >> 2;
                int kc  = (idx & 3) * 4;
                int gm  = m0 + row;
                float4 v = make_float4(0.f, 0.f, 0.f, 0.f);
                if (gm < nnodes) {
                    const float* arow = (gm < ntext) ? ent + (size_t)gm * 256 : nontext;
                    int k = k0 + kc;
                    if (k + 3 < 256) {
                        v = *(const float4*)(arow + k);
                    } else {
                        const float* x10 = g_X10 + (size_t)gm * 10;
                        float vv[4];
#pragma unroll
                        for (int j = 0; j < 4; j++) {
                            int e = k + j;
                            vv[j] = (e < 256) ? arow[e] : ((e < 266) ? x10[e - 256] : 0.f);
                        }
                        v = make_float4(vv[0], vv[1], vv[2], vv[3]);
                    }
                }
                aS[i] = v;
            }
            // ---- B ----
            {
                int krow = idx >> 5;
                int nc   = (idx & 31) * 4;
                bS[i] = *(const float4*)(g_Bc + (size_t)(k0 + krow) * CDIM + n0 + nc);
            }
        }
    };

    auto store_tile = [&](int buf) {
        uint32_t* An = As[buf];
        uint32_t* Bn = Bs[buf];
#pragma unroll
        for (int i = 0; i < 2; i++) {
            int idx = tid + i * 256;
            {
                int row = idx >> 2;
                int kc  = (idx & 3) * 4;
                uint32_t* d = An + row * AS_STRIDE + kc;
                d[0] = f2tf(aS[i].x); d[1] = f2tf(aS[i].y);
                d[2] = f2tf(aS[i].z); d[3] = f2tf(aS[i].w);
            }
            {
                int krow = idx >> 5;
                int nc   = (idx & 31) * 4;
                uint32_t* d = Bn + krow * BS_STRIDE + nc;
                d[0] = f2tf(bS[i].x); d[1] = f2tf(bS[i].y);
                d[2] = f2tf(bS[i].z); d[3] = f2tf(bS[i].w);
            }
        }
    };

    // prologue: tile 0
    load_tile(0);
    store_tile(0);
    __syncthreads();

    const int NIT = KPAD / 16;   // 17
    for (int it = 0; it < NIT; it++) {
        int buf = it & 1;
        if (it + 1 < NIT) load_tile((it + 1) * 16);

        const uint32_t* A_ = As[buf];
        const uint32_t* B_ = Bs[buf];
#pragma unroll
        for (int kk = 0; kk < 2; kk++) {
            int k8 = kk * 8;
            uint32_t af[4][4];
#pragma unroll
            for (int mt = 0; mt < 4; mt++) {
                int r0 = wm * 64 + mt * 16 + g;
                af[mt][0] = A_[r0 * AS_STRIDE + k8 + t4];
                af[mt][1] = A_[(r0 + 8) * AS_STRIDE + k8 + t4];
                af[mt][2] = A_[r0 * AS_STRIDE + k8 + t4 + 4];
                af[mt][3] = A_[(r0 + 8) * AS_STRIDE + k8 + t4 + 4];
            }
            uint32_t bf[4][2];
#pragma unroll
            for (int nt = 0; nt < 4; nt++) {
                int nb = wn * 32 + nt * 8 + g;
                bf[nt][0] = B_[(k8 + t4) * BS_STRIDE + nb];
                bf[nt][1] = B_[(k8 + t4 + 4) * BS_STRIDE + nb];
            }
#pragma unroll
            for (int mt = 0; mt < 4; mt++)
#pragma unroll
                for (int nt = 0; nt < 4; nt++)
                    mma_tf32(c[mt][nt], af[mt][0], af[mt][1], af[mt][2], af[mt][3],
                             bf[nt][0], bf[nt][1]);
        }

        if (it + 1 < NIT) store_tile(buf ^ 1);
        __syncthreads();
    }

    // store C (fp16) to g_Th
#pragma unroll
    for (int mt = 0; mt < 4; mt++) {
        int r0 = m0 + wm * 64 + mt * 16 + g;
        int r1 = r0 + 8;
#pragma unroll
        for (int nt = 0; nt < 4; nt++) {
            int cb = n0 + wn * 32 + nt * 8 + 2 * t4;
            if (r0 < nnodes)
                *(__half2*)(g_Th + (size_t)r0 * CDIM + cb) =
                    __floats2half2_rn(c[mt][nt][0], c[mt][nt][1]);
            if (r1 < nnodes)
                *(__half2*)(g_Th + (size_t)r1 * CDIM + cb) =
                    __floats2half2_rn(c[mt][nt][2], c[mt][nt][3]);
        }
    }
}

// ---------------- edge phase: out[e] = mean_s( relu(pre) . w2_s + b2_s ) ----------------
__global__ void __launch_bounds__(256)
edge_kernel(const void* __restrict__ hid, const void* __restrict__ rid,
            const void* __restrict__ tidp, float* __restrict__ out, int E) {
    __shared__ float sw2[HIDD];
    for (int i = threadIdx.x; i < HIDD; i += blockDim.x) sw2[i] = g_w2s[i];
    __syncthreads();
    int warp = threadIdx.x >> 5, lane = threadIdx.x & 31;
    int e = blockIdx.x * 8 + warp;
    if (e >= E) return;
    long h = fetch_id(hid, e);
    long t = fetch_id(tidp, e);
    long r = fetch_id(rid, e);
    const uint4* ph = (const uint4*)(g_Th + (size_t)h * CDIM);          // 160 x 8 halves
    const uint4* pt = (const uint4*)(g_Th + (size_t)t * CDIM + 1280);
    const uint4* pr = (const uint4*)(g_Rp + (size_t)r * HIDD);
    float acc = 0.f;
#pragma unroll
    for (int c = 0; c < 5; c++) {
        int idx = c * 32 + lane;          // uint4 index; element base = idx*8
        uint4 ua = ph[idx];
        uint4 ub = pt[idx];
        uint4 uq = pr[idx];
        const __half2* a2 = (const __half2*)&ua;
        const __half2* b2 = (const __half2*)&ub;
        const __half2* q2 = (const __half2*)&uq;
        const float4* w4 = (const float4*)&sw2[idx * 8];
        float4 w0 = w4[0], w1 = w4[1];
        float wv[8] = {w0.x, w0.y, w0.z, w0.w, w1.x, w1.y, w1.z, w1.w};
#pragma unroll
        for (int j = 0; j < 4; j++) {
            float2 fa = __half22float2(a2[j]);
            float2 fb = __half22float2(b2[j]);
            float2 fq = __half22float2(q2[j]);
            acc += fmaxf(fa.x + fb.x + fq.x, 0.f) * wv[2 * j];
            acc += fmaxf(fa.y + fb.y + fq.y, 0.f) * wv[2 * j + 1];
        }
    }
#pragma unroll
    for (int o = 16; o; o >>= 1) acc += __shfl_xor_sync(0xFFFFFFFFu, acc, o);
    if (lane == 0) out[e] = acc * 0.2f + g_b2mean;
}

// ---------------- host ----------------
extern "C" void kernel_launch(void* const* d_in, const int* in_sizes, int n_in,
                              void* d_out, int out_size) {
    int base = 0;
    if (n_in >= 17 && in_sizes[5] <= 16) base = 1;

    const void*  hid   = d_in[0];
    const void*  rid   = d_in[1];
    const void*  tidp  = d_in[2];
    const float* q     = (const float*)d_in[3];
    const float* ent   = (const float*)d_in[4];
    const float* rel   = (const float*)d_in[5 + base];
    const float* topic = (const float*)d_in[6 + base];
    const float* nont  = (const float*)d_in[7 + base];
    const float* w1mu  = (const float*)d_in[8 + base];
    const float* w1rho = (const float*)d_in[9 + base];
    const float* b1mu  = (const float*)d_in[10 + base];
    const float* b1rho = (const float*)d_in[11 + base];
    const float* w2mu  = (const float*)d_in[12 + base];
    const float* w2rho = (const float*)d_in[13 + base];
    const float* b2mu  = (const float*)d_in[14 + base];
    const float* b2rho = (const float*)d_in[15 + base];

    int E = in_sizes[0];
    int ntext = in_sizes[4] / 256;
    int nrel  = in_sizes[5 + base] / 256;
    int nnodes = NN;
    float* out = (float*)d_out;

    zero_kernel<<<(8 * NN + 255) / 256, 256>>>();
    detect_kernel<<<1, 1>>>((const unsigned*)hid);
    sample_w1_kernel<<<(5 * W1SZ + 255) / 256, 256>>>(w1mu, w1rho);
    sample_small_kernel<<<11, 256>>>(b1mu, b1rho, w2mu, w2rho, b2mu, b2rho);
    scat1_kernel<<<(E + 255) / 256, 256>>>(hid, tidp, topic, E);
    fin1_kernel<<<(NN + 255) / 256, 256>>>(topic);
    scat2_kernel<<<(E + 255) / 256, 256>>>(hid, tidp, E);
    fin2_kernel<<<(NN + 255) / 256, 256>>>();
    {
        int tot = KPAD * CDIM + 256 * HIDD;
        prepB_kernel<<<(tot + 255) / 256, 256>>>();
    }
    qb_kernel<<<(HIDD + 255) / 256, 256>>>(q);
    rproj_kernel<<<(nrel * HIDD + 255) / 256, 256>>>(rel, nrel);
    {
        dim3 grid(CDIM / 128, (nnodes + 127) / 128);   // x = n-tiles (20), y = m-tiles (782)
        gemm_tc_kernel<<<grid, 256>>>(ent, nont, ntext, nnodes);
    }
    edge_kernel<<<(E + 7) / 8, 256>>>(hid, rid, tidp, out, E);
}

// round 7
// speedup vs baseline: 2.1496x; 1.1254x over previous
#include <cuda_runtime.h>
#include <cuda_fp16.h>
#include <stdint.h>
#include <math.h>

// Problem constants (fixed by the dataset)
#define NN      100000          // total entities
#define NTEXTC  90000           // text entities
#define NRELC   500
#define HIDD    1280            // 5 samples * 256 hidden
#define CDIM    2560            // Hh(1280) | Ht(1280)
#define W1SZ    267264          // 256*1044
#define KPAD    272             // 256 (e0) + 10 (X10) + 6 zero pad
#define NNP     100096          // 782 * 128, padded row count for the GEMM

// ---------------- device scratch (static: no allocations allowed) ----------------
__device__ __half g_Th[(size_t)NN * CDIM];   // node tables (fp16): [n][0:1280]=Hh, [1280:2560]=Ht (~512 MB)
__device__ float g_W1[5 * W1SZ];             // sampled w1, [s][k][col] row-major (k*1044+col)
__device__ uint32_t g_Ax[(size_t)NNP * KPAD];// A operand, tf32 bits: [e0(256)|X10(10)|0(6)] (~109 MB)
__device__ uint32_t g_Bct[KPAD * CDIM];      // B operand, tf32 bits
__device__ float g_BR[256 * HIDD];           // BR[j][cc]: relation-block weights
__device__ __half g_Rp[NRELC * HIDD];        // relation proj + qproj + b1 folded in (fp16)
__device__ float g_qb[HIDD];                 // qproj + b1
__device__ float g_w2s[HIDD];                // sampled w2, [s*256+k]
__device__ float g_b2mean;
__device__ float g_b1s[5 * 256];
__device__ int   g_indeg[NN];
__device__ int   g_outdeg[NN];
// acc: [F1 | R1 | F2 | R2], each 2*NN floats
#define OFF_F1 0
#define OFF_R1 (2*NN)
#define OFF_F2 (4*NN)
#define OFF_R2 (6*NN)
__device__ float g_acc[8 * NN];
__device__ float g_X10[NN * 10];             // [topic0,topic1,f1a,f1b,f2a,f2b,r1a,r1b,r2a,r2b]
__device__ int   g_idflag;                   // 1 = ids are int64, 0 = int32

// ---------------- JAX threefry2x32 (bit-exact) ----------------
__device__ __forceinline__ void tf2x32(uint32_t k0, uint32_t k1, uint32_t c0, uint32_t c1,
                                       uint32_t& o0, uint32_t& o1) {
    uint32_t k2 = k0 ^ k1 ^ 0x1BD11BDAu;
    uint32_t x0 = c0 + k0, x1 = c1 + k1;
#define TFR(r) { x0 += x1; x1 = (x1 << (r)) | (x1 >> (32 - (r))); x1 ^= x0; }
    TFR(13) TFR(15) TFR(26) TFR(6)   x0 += k1; x1 += k2 + 1u;
    TFR(17) TFR(29) TFR(16) TFR(24)  x0 += k2; x1 += k0 + 2u;
    TFR(13) TFR(15) TFR(26) TFR(6)   x0 += k0; x1 += k1 + 3u;
    TFR(17) TFR(29) TFR(16) TFR(24)  x0 += k1; x1 += k2 + 4u;
    TFR(13) TFR(15) TFR(26) TFR(6)   x0 += k2; x1 += k0 + 5u;
#undef TFR
    o0 = x0; o1 = x1;
}

// MODERN JAX (jax_threefry_partitionable=True, default since 0.4.36):
//   fold_in(key, s) = threefry_2x32(key, (0, s))                      -> full pair
//   split(key, 4): key_j = threefry(key, (0, j))                      -> full pair (fold-like)
//   random_bits(key, 32, size): bits[i] = o0 ^ o1 of threefry(key, (hi(i), lo(i)))
__device__ __forceinline__ void sample_keys(int s, uint32_t sk[4][2]) {
    uint32_t f0, f1; tf2x32(0u, 42u, 0u, (uint32_t)s, f0, f1);   // key(42) -> fold_in(s)
#pragma unroll
    for (int j = 0; j < 4; j++)
        tf2x32(f0, f1, 0u, (uint32_t)j, sk[j][0], sk[j][1]);     // fold-like split
}

__device__ __forceinline__ uint32_t rbits32(const uint32_t k[2], uint32_t i) {
    uint32_t y0, y1; tf2x32(k[0], k[1], 0u, i, y0, y1);
    return y0 ^ y1;   // partitionable 32-bit path XOR-folds the two output words
}

// JAX: u = uniform(key, lo=nextafter(-1,0), hi=1); normal = sqrt(2)*erfinv(u)
__device__ __forceinline__ float normal_from_bits(uint32_t bits) {
    float f = __uint_as_float(0x3f800000u | (bits >> 9)) - 1.0f;   // [0,1)
    const float lo = -0.99999994f;
    float u = fmaxf(lo, fmaf(f, 2.0f, lo));
    return 1.41421356f * erfinvf(u);
}
__device__ __forceinline__ float softplus_f(float x) {
    return (x > 20.f) ? x : log1pf(expf(x));
}

// round-to-nearest fp32 -> tf32 (bit pattern in a b32 reg). RNA is load-bearing:
// truncation would introduce a systematic relative bias in the GEMM.
__device__ __forceinline__ uint32_t f2tf(float x) {
    uint32_t r; asm("cvt.rna.tf32.f32 %0, %1;" : "=r"(r) : "f"(x)); return r;
}

// ---------------- misc kernels ----------------
__global__ void zero_kernel() {
    int i = blockIdx.x * blockDim.x + threadIdx.x;
    if (i < NN)      g_indeg[i] = 0;
    if (i < NN)      g_outdeg[i] = 0;
    for (int j = i; j < 8 * NN; j += gridDim.x * blockDim.x) g_acc[j] = 0.f;
}

__global__ void detect_kernel(const unsigned* __restrict__ ids) {
    int any = 0;
    for (int i = 0; i < 128; i++) any |= (ids[2 * i + 1] != 0u);
    g_idflag = any ? 0 : 1;
}

__device__ __forceinline__ long fetch_id(const void* p, int e) {
    if (g_idflag) return (long)((const long long*)p)[e];
    return (long)((const int*)p)[e];
}

// ---------------- weight sampling (partitionable threefry) ----------------
__global__ void sample_w1_kernel(const float* __restrict__ mu, const float* __restrict__ rho) {
    int gid = blockIdx.x * blockDim.x + threadIdx.x;
    if (gid >= 5 * W1SZ) return;
    int s = gid / W1SZ;
    int i = gid - s * W1SZ;
    uint32_t sk[4][2]; sample_keys(s, sk);
    float nz = normal_from_bits(rbits32(sk[0], (uint32_t)i));
    g_W1[gid] = mu[i] + nz * softplus_f(rho[i]);
}

__global__ void sample_small_kernel(const float* __restrict__ b1mu, const float* __restrict__ b1rho,
                                    const float* __restrict__ w2mu, const float* __restrict__ w2rho,
                                    const float* __restrict__ b2mu, const float* __restrict__ b2rho) {
    int gid = blockIdx.x * blockDim.x + threadIdx.x;
    if (gid < 5 * 256) {                       // b1
        int s = gid / 256, i = gid % 256;
        uint32_t sk[4][2]; sample_keys(s, sk);
        float nz = normal_from_bits(rbits32(sk[1], (uint32_t)i));
        g_b1s[s * 256 + i] = b1mu[i] + nz * softplus_f(b1rho[i]);
    } else if (gid < 10 * 256) {               // w2
        int g = gid - 5 * 256;
        int s = g / 256, i = g % 256;
        uint32_t sk[4][2]; sample_keys(s, sk);
        float nz = normal_from_bits(rbits32(sk[2], (uint32_t)i));
        g_w2s[s * 256 + i] = w2mu[i] + nz * softplus_f(w2rho[i]);
    } else if (gid == 10 * 256) {              // b2 (scalar), averaged over samples
        float sum = 0.f;
        for (int s = 0; s < 5; s++) {
            uint32_t sk[4][2]; sample_keys(s, sk);
            float nz = normal_from_bits(rbits32(sk[3], 0u));
            sum += b2mu[0] + nz * softplus_f(b2rho[0]);
        }
        g_b2mean = sum / 5.0f;
    }
}

// ---------------- DDE (segment-mean message passing, 2-dim features) ----------------
__global__ void scat1_kernel(const void* __restrict__ hid, const void* __restrict__ tidp,
                             const float* __restrict__ topic, int E) {
    int e = blockIdx.x * blockDim.x + threadIdx.x;
    if (e >= E) return;
    long h = fetch_id(hid, e), t = fetch_id(tidp, e);
    float2 th = *(const float2*)&topic[2 * h];
    float2 tt = *(const float2*)&topic[2 * t];
    atomicAdd(&g_acc[OFF_F1 + 2 * t],     th.x);
    atomicAdd(&g_acc[OFF_F1 + 2 * t + 1], th.y);
    atomicAdd(&g_acc[OFF_R1 + 2 * h],     tt.x);
    atomicAdd(&g_acc[OFF_R1 + 2 * h + 1], tt.y);
    atomicAdd(&g_indeg[t], 1);
    atomicAdd(&g_outdeg[h], 1);
}

__global__ void fin1_kernel(const float* __restrict__ topic) {
    int n = blockIdx.x * blockDim.x + threadIdx.x;
    if (n >= NN) return;
    float di = fmaxf((float)g_indeg[n], 1.f);
    float dd = fmaxf((float)g_outdeg[n], 1.f);
    float* x = &g_X10[n * 10];
    x[0] = topic[2 * n]; x[1] = topic[2 * n + 1];
    x[2] = g_acc[OFF_F1 + 2 * n] / di;  x[3] = g_acc[OFF_F1 + 2 * n + 1] / di;
    x[6] = g_acc[OFF_R1 + 2 * n] / dd;  x[7] = g_acc[OFF_R1 + 2 * n + 1] / dd;
}

__global__ void scat2_kernel(const void* __restrict__ hid, const void* __restrict__ tidp, int E) {
    int e = blockIdx.x * blockDim.x + threadIdx.x;
    if (e >= E) return;
    long h = fetch_id(hid, e), t = fetch_id(tidp, e);
    atomicAdd(&g_acc[OFF_F2 + 2 * t],     g_X10[h * 10 + 2]);
    atomicAdd(&g_acc[OFF_F2 + 2 * t + 1], g_X10[h * 10 + 3]);
    atomicAdd(&g_acc[OFF_R2 + 2 * h],     g_X10[t * 10 + 6]);
    atomicAdd(&g_acc[OFF_R2 + 2 * h + 1], g_X10[t * 10 + 7]);
}

__global__ void fin2_kernel() {
    int n = blockIdx.x * blockDim.x + threadIdx.x;
    if (n >= NN) return;
    float di = fmaxf((float)g_indeg[n], 1.f);
    float dd = fmaxf((float)g_outdeg[n], 1.f);
    float* x = &g_X10[n * 10];
    x[4] = g_acc[OFF_F2 + 2 * n] / di;  x[5] = g_acc[OFF_F2 + 2 * n + 1] / di;
    x[8] = g_acc[OFF_R2 + 2 * n] / dd;  x[9] = g_acc[OFF_R2 + 2 * n + 1] / dd;
}

// ---------------- operand prep (tf32 pre-conversion) ----------------
// A operand: g_Ax[n][k] = tf32([e0 | X10 | 0]); rows >= nnodes zero-padded.
__global__ void prepA_kernel(const float* __restrict__ ent, const float* __restrict__ nont,
                             int ntext, int nnodes) {
    int gid = blockIdx.x * blockDim.x + threadIdx.x;
    if (gid >= NNP * KPAD) return;
    int n = gid / KPAD, k = gid - n * KPAD;
    float v = 0.f;
    if (n < nnodes) {
        if (k < 256)       v = (n < ntext) ? ent[(size_t)n * 256 + k] : nont[k];
        else if (k < 266)  v = g_X10[n * 10 + (k - 256)];
    }
    g_Ax[gid] = f2tf(v);
}

// B operand + relation-block weights.
// triple cols: [q:0-255 | h_e[h]:256-521 | h_r:522-777 | h_e[t]:778-1043]
// g_Bct row r (0..271), col c: tbl=c/1280 picks h(256)/t(778) base; rows 256..265 = X10 block; 266.. = 0
__global__ void prepB_kernel() {
    int gid = blockIdx.x * blockDim.x + threadIdx.x;
    if (gid < KPAD * CDIM) {
        int r = gid / CDIM, c = gid % CDIM;
        int tbl = c / 1280, cc = c % 1280;
        int s = cc / 256, k = cc % 256;
        int basecol = tbl ? 778 : 256;
        float v = 0.f;
        if (r < 266) v = g_W1[(size_t)s * W1SZ + k * 1044 + basecol + r];
        g_Bct[gid] = f2tf(v);
    } else if (gid < KPAD * CDIM + 256 * HIDD) {
        int idx = gid - KPAD * CDIM;
        int j = idx / HIDD, cc = idx % HIDD;
        int s = cc / 256, k = cc % 256;
        g_BR[j * HIDD + cc] = g_W1[(size_t)s * W1SZ + k * 1044 + 522 + j];
    }
}

__global__ void qb_kernel(const float* __restrict__ q) {
    int cc = blockIdx.x * blockDim.x + threadIdx.x;
    if (cc >= HIDD) return;
    int s = cc / 256, k = cc % 256;
    const float* w = &g_W1[(size_t)s * W1SZ + k * 1044];
    float sum = 0.f;
    for (int j = 0; j < 256; j++) sum += q[j] * w[j];
    g_qb[cc] = sum + g_b1s[cc];
}

__global__ void rproj_kernel(const float* __restrict__ rel, int nrel) {
    int gid = blockIdx.x * blockDim.x + threadIdx.x;
    if (gid >= nrel * HIDD) return;
    int r = gid / HIDD, cc = gid % HIDD;
    const float* rr = &rel[r * 256];
    float sum = 0.f;
    for (int j = 0; j < 256; j++) sum += rr[j] * g_BR[j * HIDD + cc];
    g_Rp[r * HIDD + cc] = __float2half_rn(sum + g_qb[cc]);   // fold qproj+b1 here (fp16 store)
}

// ---------------- main GEMM (tf32 tensor cores, preconverted operands, fp16 output) ----------------
// T[NNP, 2560] = g_Ax[NNP, 272] @ g_Bct[272, 2560]  (tf32 bits in, fp32 accum, fp16 store)
// 128x128 block tile, BK=16, 8 warps (2x4), warp tile 64x32 via m16n8k8 mma.
#define AS_STRIDE 20            // words; 80B row stride (16B-aligned, conflict-free for mma loads)
#define BS_STRIDE 132           // words; 528B row stride (16B-aligned)

__device__ __forceinline__ void mma_tf32(float c[4], uint32_t a0, uint32_t a1, uint32_t a2, uint32_t a3,
                                         uint32_t b0, uint32_t b1) {
    asm volatile(
        "mma.sync.aligned.m16n8k8.row.col.f32.tf32.tf32.f32 "
        "{%0,%1,%2,%3}, {%4,%5,%6,%7}, {%8,%9}, {%0,%1,%2,%3};"
        : "+f"(c[0]), "+f"(c[1]), "+f"(c[2]), "+f"(c[3])
        : "r"(a0), "r"(a1), "r"(a2), "r"(a3), "r"(b0), "r"(b1));
}

__global__ void __launch_bounds__(256, 2)
gemm_tc_kernel(int nnodes) {
    __shared__ __align__(16) uint32_t As[2][128 * AS_STRIDE];   // [m][k] tf32 bits
    __shared__ __align__(16) uint32_t Bs[2][16 * BS_STRIDE];    // [k][n] tf32 bits

    const int tid  = threadIdx.x;
    const int lane = tid & 31;
    const int warp = tid >> 5;
    const int wm = warp >> 2;          // 0..1
    const int wn = warp & 3;           // 0..3
    const int g  = lane >> 2;          // groupID 0..7
    const int t4 = lane & 3;           // threadID_in_group 0..3
    const int m0 = blockIdx.y * 128;
    const int n0 = blockIdx.x * 128;

    float c[4][4][4];
#pragma unroll
    for (int mt = 0; mt < 4; mt++)
#pragma unroll
        for (int nt = 0; nt < 4; nt++)
#pragma unroll
            for (int i = 0; i < 4; i++) c[mt][nt][i] = 0.f;

    // per-thread tile slots: A row=idx>>2, kc=(idx&3)*4 ; B krow=idx>>5, nc=(idx&31)*4
    uint4 aS[2], bS[2];
    const int aRow[2] = { (tid + 0)   >> 2, (tid + 256) >> 2 };
    const int aKc[2]  = { ((tid + 0) & 3) * 4, ((tid + 256) & 3) * 4 };
    const int bKr[2]  = { (tid + 0)   >> 5, (tid + 256) >> 5 };
    const int bNc[2]  = { ((tid + 0) & 31) * 4, ((tid + 256) & 31) * 4 };

    auto load_tile = [&](int k0) {
#pragma unroll
        for (int i = 0; i < 2; i++) {
            aS[i] = *(const uint4*)(g_Ax + (size_t)(m0 + aRow[i]) * KPAD + k0 + aKc[i]);
            bS[i] = *(const uint4*)(g_Bct + (size_t)(k0 + bKr[i]) * CDIM + n0 + bNc[i]);
        }
    };
    auto store_tile = [&](int buf) {
#pragma unroll
        for (int i = 0; i < 2; i++) {
            *(uint4*)(As[buf] + aRow[i] * AS_STRIDE + aKc[i]) = aS[i];
            *(uint4*)(Bs[buf] + bKr[i] * BS_STRIDE + bNc[i]) = bS[i];
        }
    };

    load_tile(0);
    store_tile(0);
    __syncthreads();

    const int NIT = KPAD / 16;   // 17
    for (int it = 0; it < NIT; it++) {
        int buf = it & 1;
        if (it + 1 < NIT) load_tile((it + 1) * 16);

        const uint32_t* A_ = As[buf];
        const uint32_t* B_ = Bs[buf];
#pragma unroll
        for (int kk = 0; kk < 2; kk++) {
            int k8 = kk * 8;
            uint32_t af[4][4];
#pragma unroll
            for (int mt = 0; mt < 4; mt++) {
                int r0 = wm * 64 + mt * 16 + g;
                af[mt][0] = A_[r0 * AS_STRIDE + k8 + t4];
                af[mt][1] = A_[(r0 + 8) * AS_STRIDE + k8 + t4];
                af[mt][2] = A_[r0 * AS_STRIDE + k8 + t4 + 4];
                af[mt][3] = A_[(r0 + 8) * AS_STRIDE + k8 + t4 + 4];
            }
            uint32_t bf[4][2];
#pragma unroll
            for (int nt = 0; nt < 4; nt++) {
                int nb = wn * 32 + nt * 8 + g;
                bf[nt][0] = B_[(k8 + t4) * BS_STRIDE + nb];
                bf[nt][1] = B_[(k8 + t4 + 4) * BS_STRIDE + nb];
            }
#pragma unroll
            for (int mt = 0; mt < 4; mt++)
#pragma unroll
                for (int nt = 0; nt < 4; nt++)
                    mma_tf32(c[mt][nt], af[mt][0], af[mt][1], af[mt][2], af[mt][3],
                             bf[nt][0], bf[nt][1]);
        }

        if (it + 1 < NIT) store_tile(buf ^ 1);
        __syncthreads();
    }

    // store C (fp16) to g_Th
#pragma unroll
    for (int mt = 0; mt < 4; mt++) {
        int r0 = m0 + wm * 64 + mt * 16 + g;
        int r1 = r0 + 8;
#pragma unroll
        for (int nt = 0; nt < 4; nt++) {
            int cb = n0 + wn * 32 + nt * 8 + 2 * t4;
            if (r0 < nnodes)
                *(__half2*)(g_Th + (size_t)r0 * CDIM + cb) =
                    __floats2half2_rn(c[mt][nt][0], c[mt][nt][1]);
            if (r1 < nnodes)
                *(__half2*)(g_Th + (size_t)r1 * CDIM + cb) =
                    __floats2half2_rn(c[mt][nt][2], c[mt][nt][3]);
        }
    }
}

// ---------------- edge phase: out[e] = mean_s( relu(pre) . w2_s + b2_s ) ----------------
__global__ void __launch_bounds__(256)
edge_kernel(const void* __restrict__ hid, const void* __restrict__ rid,
            const void* __restrict__ tidp, float* __restrict__ out, int E) {
    __shared__ float sw2[HIDD];
    for (int i = threadIdx.x; i < HIDD; i += blockDim.x) sw2[i] = g_w2s[i];
    __syncthreads();
    int warp = threadIdx.x >> 5, lane = threadIdx.x & 31;
    int e = blockIdx.x * 8 + warp;
    if (e >= E) return;
    long h = fetch_id(hid, e);
    long t = fetch_id(tidp, e);
    long r = fetch_id(rid, e);
    const uint4* ph = (const uint4*)(g_Th + (size_t)h * CDIM);          // 160 x 8 halves
    const uint4* pt = (const uint4*)(g_Th + (size_t)t * CDIM + 1280);
    const uint4* pr = (const uint4*)(g_Rp + (size_t)r * HIDD);
    float acc = 0.f;
#pragma unroll
    for (int c = 0; c < 5; c++) {
        int idx = c * 32 + lane;          // uint4 index; element base = idx*8
        uint4 ua = ph[idx];
        uint4 ub = pt[idx];
        uint4 uq = pr[idx];
        const __half2* a2 = (const __half2*)&ua;
        const __half2* b2 = (const __half2*)&ub;
        const __half2* q2 = (const __half2*)&uq;
        const float4* w4 = (const float4*)&sw2[idx * 8];
        float4 w0 = w4[0], w1 = w4[1];
        float wv[8] = {w0.x, w0.y, w0.z, w0.w, w1.x, w1.y, w1.z, w1.w};
#pragma unroll
        for (int j = 0; j < 4; j++) {
            float2 fa = __half22float2(a2[j]);
            float2 fb = __half22float2(b2[j]);
            float2 fq = __half22float2(q2[j]);
            acc += fmaxf(fa.x + fb.x + fq.x, 0.f) * wv[2 * j];
            acc += fmaxf(fa.y + fb.y + fq.y, 0.f) * wv[2 * j + 1];
        }
    }
#pragma unroll
    for (int o = 16; o; o >>= 1) acc += __shfl_xor_sync(0xFFFFFFFFu, acc, o);
    if (lane == 0) out[e] = acc * 0.2f + g_b2mean;
}

// ---------------- host ----------------
extern "C" void kernel_launch(void* const* d_in, const int* in_sizes, int n_in,
                              void* d_out, int out_size) {
    int base = 0;
    if (n_in >= 17 && in_sizes[5] <= 16) base = 1;

    const void*  hid   = d_in[0];
    const void*  rid   = d_in[1];
    const void*  tidp  = d_in[2];
    const float* q     = (const float*)d_in[3];
    const float* ent   = (const float*)d_in[4];
    const float* rel   = (const float*)d_in[5 + base];
    const float* topic = (const float*)d_in[6 + base];
    const float* nont  = (const float*)d_in[7 + base];
    const float* w1mu  = (const float*)d_in[8 + base];
    const float* w1rho = (const float*)d_in[9 + base];
    const float* b1mu  = (const float*)d_in[10 + base];
    const float* b1rho = (const float*)d_in[11 + base];
    const float* w2mu  = (const float*)d_in[12 + base];
    const float* w2rho = (const float*)d_in[13 + base];
    const float* b2mu  = (const float*)d_in[14 + base];
    const float* b2rho = (const float*)d_in[15 + base];

    int E = in_sizes[0];
    int ntext = in_sizes[4] / 256;
    int nrel  = in_sizes[5 + base] / 256;
    int nnodes = NN;
    float* out = (float*)d_out;

    zero_kernel<<<(8 * NN + 255) / 256, 256>>>();
    detect_kernel<<<1, 1>>>((const unsigned*)hid);
    sample_w1_kernel<<<(5 * W1SZ + 255) / 256, 256>>>(w1mu, w1rho);
    sample_small_kernel<<<11, 256>>>(b1mu, b1rho, w2mu, w2rho, b2mu, b2rho);
    scat1_kernel<<<(E + 255) / 256, 256>>>(hid, tidp, topic, E);
    fin1_kernel<<<(NN + 255) / 256, 256>>>(topic);
    scat2_kernel<<<(E + 255) / 256, 256>>>(hid, tidp, E);
    fin2_kernel<<<(NN + 255) / 256, 256>>>();
    prepA_kernel<<<(NNP * KPAD + 255) / 256, 256>>>(ent, nont, ntext, nnodes);
    {
        int tot = KPAD * CDIM + 256 * HIDD;
        prepB_kernel<<<(tot + 255) / 256, 256>>>();
    }
    qb_kernel<<<(HIDD + 255) / 256, 256>>>(q);
    rproj_kernel<<<(nrel * HIDD + 255) / 256, 256>>>(rel, nrel);
    {
        dim3 grid(CDIM / 128, NNP / 128);   // x = n-tiles (20), y = m-tiles (782)
        gemm_tc_kernel<<<grid, 256>>>(nnodes);
    }
    edge_kernel<<<(E + 7) / 8, 256>>>(hid, rid, tidp, out, E);
}

// round 10
// speedup vs baseline: 2.8655x; 1.3331x over previous
#include <cuda_runtime.h>
#include <cuda_fp16.h>
#include <stdint.h>
#include <math.h>

// Problem constants (fixed by the dataset)
#define NN      100000          // total entities
#define NTEXTC  90000           // text entities
#define NRELC   500
#define HIDD    1280            // 5 samples * 256 hidden
#define CDIM    2560            // Hh(1280) | Ht(1280)
#define W1SZ    267264          // 256*1044
#define KP2     288             // 256 (e0) + 10 (X10) + 22 zero pad (9 x BK32)
#define NNP     100096          // 782 * 128, padded row count for the GEMM

// ---------------- device scratch (static: no allocations allowed) ----------------
__device__ __half g_Th[(size_t)NN * CDIM];   // node tables (fp16): [n][0:1280]=Hh, [1280:2560]=Ht (~512 MB)
__device__ float g_W1[5 * W1SZ];             // sampled w1, [s][k][col] row-major (k*1044+col)
__device__ __half g_Axh[(size_t)NNP * KP2];  // A operand fp16: [e0(256)|X10(10)|0] (~58 MB)
__device__ __half g_Bh[(size_t)CDIM * KP2];  // B operand fp16, TRANSPOSED [n][k] (~1.5 MB, L2-resident)
__device__ float g_BR[256 * HIDD];           // BR[j][cc]: relation-block weights
__device__ __half g_Rp[NRELC * HIDD];        // relation proj + qproj + b1 folded in (fp16)
__device__ float g_qb[HIDD];                 // qproj + b1
__device__ float g_w2s[HIDD];                // sampled w2, [s*256+k]
__device__ float g_b2mean;
__device__ float g_b1s[5 * 256];
__device__ int   g_indeg[NN];
__device__ int   g_outdeg[NN];
// acc: [F1 | R1 | F2 | R2], each 2*NN floats
#define OFF_F1 0
#define OFF_R1 (2*NN)
#define OFF_F2 (4*NN)
#define OFF_R2 (6*NN)
__device__ float g_acc[8 * NN];
__device__ float g_X10[NN * 10];             // [topic0,topic1,f1a,f1b,f2a,f2b,r1a,r1b,r2a,r2b]
__device__ int   g_idflag;                   // 1 = ids are int64, 0 = int32

// ---------------- JAX threefry2x32 (bit-exact) ----------------
__device__ __forceinline__ void tf2x32(uint32_t k0, uint32_t k1, uint32_t c0, uint32_t c1,
                                       uint32_t& o0, uint32_t& o1) {
    uint32_t k2 = k0 ^ k1 ^ 0x1BD11BDAu;
    uint32_t x0 = c0 + k0, x1 = c1 + k1;
#define TFR(r) { x0 += x1; x1 = (x1 << (r)) | (x1 >> (32 - (r))); x1 ^= x0; }
    TFR(13) TFR(15) TFR(26) TFR(6)   x0 += k1; x1 += k2 + 1u;
    TFR(17) TFR(29) TFR(16) TFR(24)  x0 += k2; x1 += k0 + 2u;
    TFR(13) TFR(15) TFR(26) TFR(6)   x0 += k0; x1 += k1 + 3u;
    TFR(17) TFR(29) TFR(16) TFR(24)  x0 += k1; x1 += k2 + 4u;
    TFR(13) TFR(15) TFR(26) TFR(6)   x0 += k2; x1 += k0 + 5u;
#undef TFR
    o0 = x0; o1 = x1;
}

// MODERN JAX (jax_threefry_partitionable=True, default since 0.4.36):
//   fold_in(key, s) = threefry_2x32(key, (0, s))                      -> full pair
//   split(key, 4): key_j = threefry(key, (0, j))                      -> full pair (fold-like)
//   random_bits(key, 32, size): bits[i] = o0 ^ o1 of threefry(key, (hi(i), lo(i)))
__device__ __forceinline__ void sample_keys(int s, uint32_t sk[4][2]) {
    uint32_t f0, f1; tf2x32(0u, 42u, 0u, (uint32_t)s, f0, f1);   // key(42) -> fold_in(s)
#pragma unroll
    for (int j = 0; j < 4; j++)
        tf2x32(f0, f1, 0u, (uint32_t)j, sk[j][0], sk[j][1]);     // fold-like split
}

__device__ __forceinline__ uint32_t rbits32(const uint32_t k[2], uint32_t i) {
    uint32_t y0, y1; tf2x32(k[0], k[1], 0u, i, y0, y1);
    return y0 ^ y1;   // partitionable 32-bit path XOR-folds the two output words
}

// JAX: u = uniform(key, lo=nextafter(-1,0), hi=1); normal = sqrt(2)*erfinv(u)
__device__ __forceinline__ float normal_from_bits(uint32_t bits) {
    float f = __uint_as_float(0x3f800000u | (bits >> 9)) - 1.0f;   // [0,1)
    const float lo = -0.99999994f;
    float u = fmaxf(lo, fmaf(f, 2.0f, lo));
    return 1.41421356f * erfinvf(u);
}
__device__ __forceinline__ float softplus_f(float x) {
    return (x > 20.f) ? x : log1pf(expf(x));
}

// ---------------- misc kernels ----------------
__global__ void zero_kernel() {
    int i = blockIdx.x * blockDim.x + threadIdx.x;
    if (i < NN)      g_indeg[i] = 0;
    if (i < NN)      g_outdeg[i] = 0;
    for (int j = i; j < 8 * NN; j += gridDim.x * blockDim.x) g_acc[j] = 0.f;
}

__global__ void detect_kernel(const unsigned* __restrict__ ids) {
    int any = 0;
    for (int i = 0; i < 128; i++) any |= (ids[2 * i + 1] != 0u);
    g_idflag = any ? 0 : 1;
}

__device__ __forceinline__ long fetch_id(const void* p, int e) {
    if (g_idflag) return (long)((const long long*)p)[e];
    return (long)((const int*)p)[e];
}

// ---------------- weight sampling (partitionable threefry) ----------------
__global__ void sample_w1_kernel(const float* __restrict__ mu, const float* __restrict__ rho) {
    int gid = blockIdx.x * blockDim.x + threadIdx.x;
    if (gid >= 5 * W1SZ) return;
    int s = gid / W1SZ;
    int i = gid - s * W1SZ;
    uint32_t sk[4][2]; sample_keys(s, sk);
    float nz = normal_from_bits(rbits32(sk[0], (uint32_t)i));
    g_W1[gid] = mu[i] + nz * softplus_f(rho[i]);
}

__global__ void sample_small_kernel(const float* __restrict__ b1mu, const float* __restrict__ b1rho,
                                    const float* __restrict__ w2mu, const float* __restrict__ w2rho,
                                    const float* __restrict__ b2mu, const float* __restrict__ b2rho) {
    int gid = blockIdx.x * blockDim.x + threadIdx.x;
    if (gid < 5 * 256) {                       // b1
        int s = gid / 256, i = gid % 256;
        uint32_t sk[4][2]; sample_keys(s, sk);
        float nz = normal_from_bits(rbits32(sk[1], (uint32_t)i));
        g_b1s[s * 256 + i] = b1mu[i] + nz * softplus_f(b1rho[i]);
    } else if (gid < 10 * 256) {               // w2
        int g = gid - 5 * 256;
        int s = g / 256, i = g % 256;
        uint32_t sk[4][2]; sample_keys(s, sk);
        float nz = normal_from_bits(rbits32(sk[2], (uint32_t)i));
        g_w2s[s * 256 + i] = w2mu[i] + nz * softplus_f(w2rho[i]);
    } else if (gid == 10 * 256) {              // b2 (scalar), averaged over samples
        float sum = 0.f;
        for (int s = 0; s < 5; s++) {
            uint32_t sk[4][2]; sample_keys(s, sk);
            float nz = normal_from_bits(rbits32(sk[3], 0u));
            sum += b2mu[0] + nz * softplus_f(b2rho[0]);
        }
        g_b2mean = sum / 5.0f;
    }
}

// ---------------- DDE (segment-mean message passing, 2-dim features) ----------------
__global__ void scat1_kernel(const void* __restrict__ hid, const void* __restrict__ tidp,
                             const float* __restrict__ topic, int E) {
    int e = blockIdx.x * blockDim.x + threadIdx.x;
    if (e >= E) return;
    long h = fetch_id(hid, e), t = fetch_id(tidp, e);
    float2 th = *(const float2*)&topic[2 * h];
    float2 tt = *(const float2*)&topic[2 * t];
    atomicAdd(&g_acc[OFF_F1 + 2 * t],     th.x);
    atomicAdd(&g_acc[OFF_F1 + 2 * t + 1], th.y);
    atomicAdd(&g_acc[OFF_R1 + 2 * h],     tt.x);
    atomicAdd(&g_acc[OFF_R1 + 2 * h + 1], tt.y);
    atomicAdd(&g_indeg[t], 1);
    atomicAdd(&g_outdeg[h], 1);
}

__global__ void fin1_kernel(const float* __restrict__ topic) {
    int n = blockIdx.x * blockDim.x + threadIdx.x;
    if (n >= NN) return;
    float di = fmaxf((float)g_indeg[n], 1.f);
    float dd = fmaxf((float)g_outdeg[n], 1.f);
    float* x = &g_X10[n * 10];
    x[0] = topic[2 * n]; x[1] = topic[2 * n + 1];
    x[2] = g_acc[OFF_F1 + 2 * n] / di;  x[3] = g_acc[OFF_F1 + 2 * n + 1] / di;
    x[6] = g_acc[OFF_R1 + 2 * n] / dd;  x[7] = g_acc[OFF_R1 + 2 * n + 1] / dd;
}

__global__ void scat2_kernel(const void* __restrict__ hid, const void* __restrict__ tidp, int E) {
    int e = blockIdx.x * blockDim.x + threadIdx.x;
    if (e >= E) return;
    long h = fetch_id(hid, e), t = fetch_id(tidp, e);
    atomicAdd(&g_acc[OFF_F2 + 2 * t],     g_X10[h * 10 + 2]);
    atomicAdd(&g_acc[OFF_F2 + 2 * t + 1], g_X10[h * 10 + 3]);
    atomicAdd(&g_acc[OFF_R2 + 2 * h],     g_X10[t * 10 + 6]);
    atomicAdd(&g_acc[OFF_R2 + 2 * h + 1], g_X10[t * 10 + 7]);
}

__global__ void fin2_kernel() {
    int n = blockIdx.x * blockDim.x + threadIdx.x;
    if (n >= NN) return;
    float di = fmaxf((float)g_indeg[n], 1.f);
    float dd = fmaxf((float)g_outdeg[n], 1.f);
    float* x = &g_X10[n * 10];
    x[4] = g_acc[OFF_F2 + 2 * n] / di;  x[5] = g_acc[OFF_F2 + 2 * n + 1] / di;
    x[8] = g_acc[OFF_R2 + 2 * n] / dd;  x[9] = g_acc[OFF_R2 + 2 * n + 1] / dd;
}

// ---------------- operand prep (fp16) ----------------
// A operand: g_Axh[n][k] = fp16([e0 | X10 | 0]); rows >= nnodes zero-padded.
__global__ void prepA_kernel(const float* __restrict__ ent, const float* __restrict__ nont,
                             int ntext, int nnodes) {
    long gid = (long)blockIdx.x * blockDim.x + threadIdx.x;
    if (gid >= (long)NNP * KP2) return;
    int n = (int)(gid / KP2), k = (int)(gid - (long)n * KP2);
    float v = 0.f;
    if (n < nnodes) {
        if (k < 256)       v = (n < ntext) ? ent[(size_t)n * 256 + k] : nont[k];
        else if (k < 266)  v = g_X10[n * 10 + (k - 256)];
    }
    g_Axh[gid] = __float2half_rn(v);
}

// B operand (TRANSPOSED [n][k]) + relation-block weights.
// triple cols: [q:0-255 | h_e[h]:256-521 | h_r:522-777 | h_e[t]:778-1043]
// g_Bh[c][r]: tbl=c/1280 picks h(256)/t(778) base col; rows 256..265 = X10 block; 266.. = 0
__global__ void prepB_kernel() {
    int gid = blockIdx.x * blockDim.x + threadIdx.x;
    if (gid < CDIM * KP2) {
        int c = gid / KP2, r = gid - c * KP2;
        int tbl = c / 1280, cc = c % 1280;
        int s = cc / 256, k = cc % 256;
        int basecol = tbl ? 778 : 256;
        float v = 0.f;
        if (r < 266) v = g_W1[(size_t)s * W1SZ + k * 1044 + basecol + r];
        g_Bh[gid] = __float2half_rn(v);
    } else if (gid < CDIM * KP2 + 256 * HIDD) {
        int idx = gid - CDIM * KP2;
        int j = idx / HIDD, cc = idx % HIDD;
        int s = cc / 256, k = cc % 256;
        g_BR[j * HIDD + cc] = g_W1[(size_t)s * W1SZ + k * 1044 + 522 + j];
    }
}

__global__ void qb_kernel(const float* __restrict__ q) {
    int cc = blockIdx.x * blockDim.x + threadIdx.x;
    if (cc >= HIDD) return;
    int s = cc / 256, k = cc % 256;
    const float* w = &g_W1[(size_t)s * W1SZ + k * 1044];
    float sum = 0.f;
    for (int j = 0; j < 256; j++) sum += q[j] * w[j];
    g_qb[cc] = sum + g_b1s[cc];
}

__global__ void rproj_kernel(const float* __restrict__ rel, int nrel) {
    int gid = blockIdx.x * blockDim.x + threadIdx.x;
    if (gid >= nrel * HIDD) return;
    int r = gid / HIDD, cc = gid % HIDD;
    const float* rr = &rel[r * 256];
    float sum = 0.f;
    for (int j = 0; j < 256; j++) sum += rr[j] * g_BR[j * HIDD + cc];
    g_Rp[r * HIDD + cc] = __float2half_rn(sum + g_qb[cc]);   // fold qproj+b1 here (fp16 store)
}

// ---------------- main GEMM (fp16 tensor cores m16n8k16, fp32 accum, fp16 out) ----------------
// T[NNP, 2560] = g_Axh[NNP, 288] @ g_Bh[2560, 288]^T
// 128x128 block tile, BK=32, 8 warps (2x4), warp tile 64x32.
// smem word stride 20 (= 32 halves data + 8 halves pad): conflict-free for frag loads.
#define SM_STRIDE 20            // 32-bit words per row (A: [m][k], B: [n][k])

__device__ __forceinline__ void mma_f16(float c[4], uint32_t a0, uint32_t a1, uint32_t a2, uint32_t a3,
                                        uint32_t b0, uint32_t b1) {
    asm volatile(
        "mma.sync.aligned.m16n8k16.row.col.f32.f16.f16.f32 "
        "{%0,%1,%2,%3}, {%4,%5,%6,%7}, {%8,%9}, {%0,%1,%2,%3};"
        : "+f"(c[0]), "+f"(c[1]), "+f"(c[2]), "+f"(c[3])
        : "r"(a0), "r"(a1), "r"(a2), "r"(a3), "r"(b0), "r"(b1));
}

__global__ void __launch_bounds__(256, 2)
gemm_tc_kernel(int nnodes) {
    __shared__ __align__(16) uint32_t As[2][128 * SM_STRIDE];   // [m][k] f16x2 words
    __shared__ __align__(16) uint32_t Bs[2][128 * SM_STRIDE];   // [n][k] f16x2 words

    const int tid  = threadIdx.x;
    const int lane = tid & 31;
    const int warp = tid >> 5;
    const int wm = warp >> 2;          // 0..1
    const int wn = warp & 3;           // 0..3
    const int g  = lane >> 2;          // groupID 0..7
    const int t4 = lane & 3;           // threadID_in_group 0..3
    const int m0 = blockIdx.y * 128;
    const int n0 = blockIdx.x * 128;

    float c[4][4][4];
#pragma unroll
    for (int mt = 0; mt < 4; mt++)
#pragma unroll
        for (int nt = 0; nt < 4; nt++)
#pragma unroll
            for (int i = 0; i < 4; i++) c[mt][nt][i] = 0.f;

    // tile load mapping: 128 rows x 32 halves = 512 uint4; thread handles idx = tid, tid+256
    // row = idx>>2, kq = (idx&3) (uint4 = 8 halves = 4 words)
    uint4 aS[2], bS[2];
    const int ldRow[2] = { (tid + 0) >> 2, (tid + 256) >> 2 };
    const int ldKq[2]  = { (tid + 0) & 3, (tid + 256) & 3 };

    auto load_tile = [&](int k0) {
#pragma unroll
        for (int i = 0; i < 2; i++) {
            aS[i] = *(const uint4*)(g_Axh + (size_t)(m0 + ldRow[i]) * KP2 + k0 + ldKq[i] * 8);
            bS[i] = *(const uint4*)(g_Bh  + (size_t)(n0 + ldRow[i]) * KP2 + k0 + ldKq[i] * 8);
        }
    };
    auto store_tile = [&](int buf) {
#pragma unroll
        for (int i = 0; i < 2; i++) {
            *(uint4*)(As[buf] + ldRow[i] * SM_STRIDE + ldKq[i] * 4) = aS[i];
            *(uint4*)(Bs[buf] + ldRow[i] * SM_STRIDE + ldKq[i] * 4) = bS[i];
        }
    };

    load_tile(0);
    store_tile(0);
    __syncthreads();

    const int NIT = KP2 / 32;   // 9
    for (int it = 0; it < NIT; it++) {
        int buf = it & 1;
        if (it + 1 < NIT) load_tile((it + 1) * 32);

        const uint32_t* A_ = As[buf];
        const uint32_t* B_ = Bs[buf];
#pragma unroll
        for (int kk = 0; kk < 2; kk++) {        // two k16 steps within BK=32
            int kw = kk * 8;                    // word offset
            uint32_t af[4][4];
#pragma unroll
            for (int mt = 0; mt < 4; mt++) {
                int r0 = wm * 64 + mt * 16 + g;
                af[mt][0] = A_[r0 * SM_STRIDE + kw + t4];
                af[mt][1] = A_[(r0 + 8) * SM_STRIDE + kw + t4];
                af[mt][2] = A_[r0 * SM_STRIDE + kw + 4 + t4];
                af[mt][3] = A_[(r0 + 8) * SM_STRIDE + kw + 4 + t4];
            }
            uint32_t bf[4][2];
#pragma unroll
            for (int nt = 0; nt < 4; nt++) {
                int nb = wn * 32 + nt * 8 + g;
                bf[nt][0] = B_[nb * SM_STRIDE + kw + t4];
                bf[nt][1] = B_[nb * SM_STRIDE + kw + 4 + t4];
            }
#pragma unroll
            for (int mt = 0; mt < 4; mt++)
#pragma unroll
                for (int nt = 0; nt < 4; nt++)
                    mma_f16(c[mt][nt], af[mt][0], af[mt][1], af[mt][2], af[mt][3],
                            bf[nt][0], bf[nt][1]);
        }

        if (it + 1 < NIT) store_tile(buf ^ 1);
        __syncthreads();
    }

    // store C (fp16) to g_Th
#pragma unroll
    for (int mt = 0; mt < 4; mt++) {
        int r0 = m0 + wm * 64 + mt * 16 + g;
        int r1 = r0 + 8;
#pragma unroll
        for (int nt = 0; nt < 4; nt++) {
            int cb = n0 + wn * 32 + nt * 8 + 2 * t4;
            if (r0 < nnodes)
                *(__half2*)(g_Th + (size_t)r0 * CDIM + cb) =
                    __floats2half2_rn(c[mt][nt][0], c[mt][nt][1]);
            if (r1 < nnodes)
                *(__half2*)(g_Th + (size_t)r1 * CDIM + cb) =
                    __floats2half2_rn(c[mt][nt][2], c[mt][nt][3]);
        }
    }
}

// ---------------- edge phase: out[e] = mean_s( relu(pre) . w2_s + b2_s ) ----------------
__global__ void __launch_bounds__(256)
edge_kernel(const void* __restrict__ hid, const void* __restrict__ rid,
            const void* __restrict__ tidp, float* __restrict__ out, int E) {
    __shared__ float sw2[HIDD];
    for (int i = threadIdx.x; i < HIDD; i += blockDim.x) sw2[i] = g_w2s[i];
    __syncthreads();
    int warp = threadIdx.x >> 5, lane = threadIdx.x & 31;
    int e = blockIdx.x * 8 + warp;
    if (e >= E) return;
    long h = fetch_id(hid, e);
    long t = fetch_id(tidp, e);
    long r = fetch_id(rid, e);
    const uint4* ph = (const uint4*)(g_Th + (size_t)h * CDIM);          // 160 x 8 halves
    const uint4* pt = (const uint4*)(g_Th + (size_t)t * CDIM + 1280);
    const uint4* pr = (const uint4*)(g_Rp + (size_t)r * HIDD);
    float acc = 0.f;
#pragma unroll
    for (int c = 0; c < 5; c++) {
        int idx = c * 32 + lane;          // uint4 index; element base = idx*8
        uint4 ua = ph[idx];
        uint4 ub = pt[idx];
        uint4 uq = pr[idx];
        const __half2* a2 = (const __half2*)&ua;
        const __half2* b2 = (const __half2*)&ub;
        const __half2* q2 = (const __half2*)&uq;
        const float4* w4 = (const float4*)&sw2[idx * 8];
        float4 w0 = w4[0], w1 = w4[1];
        float wv[8] = {w0.x, w0.y, w0.z, w0.w, w1.x, w1.y, w1.z, w1.w};
#pragma unroll
        for (int j = 0; j < 4; j++) {
            float2 fa = __half22float2(a2[j]);
            float2 fb = __half22float2(b2[j]);
            float2 fq = __half22float2(q2[j]);
            acc += fmaxf(fa.x + fb.x + fq.x, 0.f) * wv[2 * j];
            acc += fmaxf(fa.y + fb.y + fq.y, 0.f) * wv[2 * j + 1];
        }
    }
#pragma unroll
    for (int o = 16; o; o >>= 1) acc += __shfl_xor_sync(0xFFFFFFFFu, acc, o);
    if (lane == 0) out[e] = acc * 0.2f + g_b2mean;
}

// ---------------- host ----------------
extern "C" void kernel_launch(void* const* d_in, const int* in_sizes, int n_in,
                              void* d_out, int out_size) {
    int base = 0;
    if (n_in >= 17 && in_sizes[5] <= 16) base = 1;

    const void*  hid   = d_in[0];
    const void*  rid   = d_in[1];
    const void*  tidp  = d_in[2];
    const float* q     = (const float*)d_in[3];
    const float* ent   = (const float*)d_in[4];
    const float* rel   = (const float*)d_in[5 + base];
    const float* topic = (const float*)d_in[6 + base];
    const float* nont  = (const float*)d_in[7 + base];
    const float* w1mu  = (const float*)d_in[8 + base];
    const float* w1rho = (const float*)d_in[9 + base];
    const float* b1mu  = (const float*)d_in[10 + base];
    const float* b1rho = (const float*)d_in[11 + base];
    const float* w2mu  = (const float*)d_in[12 + base];
    const float* w2rho = (const float*)d_in[13 + base];
    const float* b2mu  = (const float*)d_in[14 + base];
    const float* b2rho = (const float*)d_in[15 + base];

    int E = in_sizes[0];
    int ntext = in_sizes[4] / 256;
    int nrel  = in_sizes[5 + base] / 256;
    int nnodes = NN;
    float* out = (float*)d_out;

    zero_kernel<<<(8 * NN + 255) / 256, 256>>>();
    detect_kernel<<<1, 1>>>((const unsigned*)hid);
    sample_w1_kernel<<<(5 * W1SZ + 255) / 256, 256>>>(w1mu, w1rho);
    sample_small_kernel<<<11, 256>>>(b1mu, b1rho, w2mu, w2rho, b2mu, b2rho);
    scat1_kernel<<<(E + 255) / 256, 256>>>(hid, tidp, topic, E);
    fin1_kernel<<<(NN + 255) / 256, 256>>>(topic);
    scat2_kernel<<<(E + 255) / 256, 256>>>(hid, tidp, E);
    fin2_kernel<<<(NN + 255) / 256, 256>>>();
    {
        long totA = (long)NNP * KP2;
        prepA_kernel<<<(int)((totA + 255) / 256), 256>>>(ent, nont, ntext, nnodes);
    }
    {
        int tot = CDIM * KP2 + 256 * HIDD;
        prepB_kernel<<<(tot + 255) / 256, 256>>>();
    }
    qb_kernel<<<(HIDD + 255) / 256, 256>>>(q);
    rproj_kernel<<<(nrel * HIDD + 255) / 256, 256>>>(rel, nrel);
    {
        dim3 grid(CDIM / 128, NNP / 128);   // x = n-tiles (20), y = m-tiles (782)
        gemm_tc_kernel<<<grid, 256>>>(nnodes);
    }
    edge_kernel<<<(E + 7) / 8, 256>>>(hid, rid, tidp, out, E);
}

// round 11
// speedup vs baseline: 2.8826x; 1.0060x over previous
#include <cuda_runtime.h>
#include <cuda_fp16.h>
#include <stdint.h>
#include <math.h>

// Problem constants (fixed by the dataset)
#define NN      100000          // total entities
#define NTEXTC  90000           // text entities
#define NRELC   500
#define HIDD    1280            // 5 samples * 256 hidden
#define CDIM    2560            // Hh(1280) | Ht(1280)
#define W1SZ    267264          // 256*1044
#define KP2     288             // 256 (e0) + 10 (X10) + 22 zero pad (9 x BK32)
#define NNP     100096          // 782 * 128, padded row count for the GEMM

// ---------------- device scratch (static: no allocations allowed) ----------------
__device__ __half g_Th[(size_t)NN * CDIM];   // node tables (fp16): [n][0:1280]=Hh, [1280:2560]=Ht (~512 MB)
__device__ float g_W1[5 * W1SZ];             // sampled w1, [s][k][col] row-major (k*1044+col)
__device__ __half g_Axh[(size_t)NNP * KP2];  // A operand fp16: [e0(256)|X10(10)|0] (~58 MB)
__device__ __half g_Bh[(size_t)CDIM * KP2];  // B operand fp16, TRANSPOSED [n][k] (~1.5 MB, L2-resident)
__device__ float g_BR[256 * HIDD];           // BR[j][cc]: relation-block weights
__device__ __half g_Rp[NRELC * HIDD];        // relation proj + qproj + b1 folded in (fp16)
__device__ float g_qb[HIDD];                 // qproj + b1
__device__ float g_w2s[HIDD];                // sampled w2, [s*256+k]
__device__ float g_b2mean;
__device__ float g_b1s[5 * 256];
__device__ int   g_indeg[NN];
__device__ int   g_outdeg[NN];
__device__ uint32_t g_wk[5][2];              // hoisted w1 sampling keys (fold_in(42,s) -> split[0])
// acc: [F1 | R1 | F2 | R2], each 2*NN floats
#define OFF_F1 0
#define OFF_R1 (2*NN)
#define OFF_F2 (4*NN)
#define OFF_R2 (6*NN)
__device__ float g_acc[8 * NN];
__device__ float g_X10[NN * 10];             // [topic0,topic1,f1a,f1b,f2a,f2b,r1a,r1b,r2a,r2b]
__device__ int   g_idflag;                   // 1 = ids are int64, 0 = int32

// ---------------- JAX threefry2x32 (bit-exact) ----------------
__device__ __forceinline__ void tf2x32(uint32_t k0, uint32_t k1, uint32_t c0, uint32_t c1,
                                       uint32_t& o0, uint32_t& o1) {
    uint32_t k2 = k0 ^ k1 ^ 0x1BD11BDAu;
    uint32_t x0 = c0 + k0, x1 = c1 + k1;
#define TFR(r) { x0 += x1; x1 = (x1 << (r)) | (x1 >> (32 - (r))); x1 ^= x0; }
    TFR(13) TFR(15) TFR(26) TFR(6)   x0 += k1; x1 += k2 + 1u;
    TFR(17) TFR(29) TFR(16) TFR(24)  x0 += k2; x1 += k0 + 2u;
    TFR(13) TFR(15) TFR(26) TFR(6)   x0 += k0; x1 += k1 + 3u;
    TFR(17) TFR(29) TFR(16) TFR(24)  x0 += k1; x1 += k2 + 4u;
    TFR(13) TFR(15) TFR(26) TFR(6)   x0 += k2; x1 += k0 + 5u;
#undef TFR
    o0 = x0; o1 = x1;
}

// MODERN JAX (jax_threefry_partitionable=True, default since 0.4.36):
//   fold_in(key, s) = threefry_2x32(key, (0, s))                      -> full pair
//   split(key, 4): key_j = threefry(key, (0, j))                      -> full pair (fold-like)
//   random_bits(key, 32, size): bits[i] = o0 ^ o1 of threefry(key, (hi(i), lo(i)))
__device__ __forceinline__ void sample_keys(int s, uint32_t sk[4][2]) {
    uint32_t f0, f1; tf2x32(0u, 42u, 0u, (uint32_t)s, f0, f1);   // key(42) -> fold_in(s)
#pragma unroll
    for (int j = 0; j < 4; j++)
        tf2x32(f0, f1, 0u, (uint32_t)j, sk[j][0], sk[j][1]);     // fold-like split
}

__device__ __forceinline__ uint32_t rbits32(const uint32_t k[2], uint32_t i) {
    uint32_t y0, y1; tf2x32(k[0], k[1], 0u, i, y0, y1);
    return y0 ^ y1;   // partitionable 32-bit path XOR-folds the two output words
}

// JAX: u = uniform(key, lo=nextafter(-1,0), hi=1); normal = sqrt(2)*erfinv(u)
__device__ __forceinline__ float normal_from_bits(uint32_t bits) {
    float f = __uint_as_float(0x3f800000u | (bits >> 9)) - 1.0f;   // [0,1)
    const float lo = -0.99999994f;
    float u = fmaxf(lo, fmaf(f, 2.0f, lo));
    return 1.41421356f * erfinvf(u);
}
__device__ __forceinline__ float softplus_f(float x) {
    return (x > 20.f) ? x : log1pf(expf(x));
}

// ---------------- misc kernels ----------------
__global__ void zero_kernel() {
    int i = blockIdx.x * blockDim.x + threadIdx.x;
    if (i < NN)      g_indeg[i] = 0;
    if (i < NN)      g_outdeg[i] = 0;
    for (int j = i; j < 8 * NN; j += gridDim.x * blockDim.x) g_acc[j] = 0.f;
}

__global__ void detect_kernel(const unsigned* __restrict__ ids) {
    int any = 0;
    for (int i = 0; i < 128; i++) any |= (ids[2 * i + 1] != 0u);
    g_idflag = any ? 0 : 1;
    // hoist the w1 sampling keys: fold_in(key42, s) -> fold-like split j=0
    for (int s = 0; s < 5; s++) {
        uint32_t f0, f1; tf2x32(0u, 42u, 0u, (uint32_t)s, f0, f1);
        uint32_t k0, k1; tf2x32(f0, f1, 0u, 0u, k0, k1);
        g_wk[s][0] = k0; g_wk[s][1] = k1;
    }
}

__device__ __forceinline__ long fetch_id(const void* p, int e) {
    if (g_idflag) return (long)((const long long*)p)[e];
    return (long)((const int*)p)[e];
}

// ---------------- weight sampling (partitionable threefry) ----------------
__global__ void sample_w1_kernel(const float* __restrict__ mu, const float* __restrict__ rho) {
    int gid = blockIdx.x * blockDim.x + threadIdx.x;
    if (gid >= 5 * W1SZ) return;
    int s = gid / W1SZ;
    int i = gid - s * W1SZ;
    uint32_t k[2] = { g_wk[s][0], g_wk[s][1] };        // hoisted key: ONE hash per element
    float nz = normal_from_bits(rbits32(k, (uint32_t)i));
    g_W1[gid] = mu[i] + nz * softplus_f(rho[i]);
}

__global__ void sample_small_kernel(const float* __restrict__ b1mu, const float* __restrict__ b1rho,
                                    const float* __restrict__ w2mu, const float* __restrict__ w2rho,
                                    const float* __restrict__ b2mu, const float* __restrict__ b2rho) {
    int gid = blockIdx.x * blockDim.x + threadIdx.x;
    if (gid < 5 * 256) {                       // b1
        int s = gid / 256, i = gid % 256;
        uint32_t sk[4][2]; sample_keys(s, sk);
        float nz = normal_from_bits(rbits32(sk[1], (uint32_t)i));
        g_b1s[s * 256 + i] = b1mu[i] + nz * softplus_f(b1rho[i]);
    } else if (gid < 10 * 256) {               // w2
        int g = gid - 5 * 256;
        int s = g / 256, i = g % 256;
        uint32_t sk[4][2]; sample_keys(s, sk);
        float nz = normal_from_bits(rbits32(sk[2], (uint32_t)i));
        g_w2s[s * 256 + i] = w2mu[i] + nz * softplus_f(w2rho[i]);
    } else if (gid == 10 * 256) {              // b2 (scalar), averaged over samples
        float sum = 0.f;
        for (int s = 0; s < 5; s++) {
            uint32_t sk[4][2]; sample_keys(s, sk);
            float nz = normal_from_bits(rbits32(sk[3], 0u));
            sum += b2mu[0] + nz * softplus_f(b2rho[0]);
        }
        g_b2mean = sum / 5.0f;
    }
}

// ---------------- DDE (segment-mean message passing, 2-dim features) ----------------
__global__ void scat1_kernel(const void* __restrict__ hid, const void* __restrict__ tidp,
                             const float* __restrict__ topic, int E) {
    int e = blockIdx.x * blockDim.x + threadIdx.x;
    if (e >= E) return;
    long h = fetch_id(hid, e), t = fetch_id(tidp, e);
    float2 th = *(const float2*)&topic[2 * h];
    float2 tt = *(const float2*)&topic[2 * t];
    atomicAdd(&g_acc[OFF_F1 + 2 * t],     th.x);
    atomicAdd(&g_acc[OFF_F1 + 2 * t + 1], th.y);
    atomicAdd(&g_acc[OFF_R1 + 2 * h],     tt.x);
    atomicAdd(&g_acc[OFF_R1 + 2 * h + 1], tt.y);
    atomicAdd(&g_indeg[t], 1);
    atomicAdd(&g_outdeg[h], 1);
}

__global__ void fin1_kernel(const float* __restrict__ topic) {
    int n = blockIdx.x * blockDim.x + threadIdx.x;
    if (n >= NN) return;
    float di = fmaxf((float)g_indeg[n], 1.f);
    float dd = fmaxf((float)g_outdeg[n], 1.f);
    float* x = &g_X10[n * 10];
    x[0] = topic[2 * n]; x[1] = topic[2 * n + 1];
    x[2] = g_acc[OFF_F1 + 2 * n] / di;  x[3] = g_acc[OFF_F1 + 2 * n + 1] / di;
    x[6] = g_acc[OFF_R1 + 2 * n] / dd;  x[7] = g_acc[OFF_R1 + 2 * n + 1] / dd;
}

__global__ void scat2_kernel(const void* __restrict__ hid, const void* __restrict__ tidp, int E) {
    int e = blockIdx.x * blockDim.x + threadIdx.x;
    if (e >= E) return;
    long h = fetch_id(hid, e), t = fetch_id(tidp, e);
    atomicAdd(&g_acc[OFF_F2 + 2 * t],     g_X10[h * 10 + 2]);
    atomicAdd(&g_acc[OFF_F2 + 2 * t + 1], g_X10[h * 10 + 3]);
    atomicAdd(&g_acc[OFF_R2 + 2 * h],     g_X10[t * 10 + 6]);
    atomicAdd(&g_acc[OFF_R2 + 2 * h + 1], g_X10[t * 10 + 7]);
}

__global__ void fin2_kernel() {
    int n = blockIdx.x * blockDim.x + threadIdx.x;
    if (n >= NN) return;
    float di = fmaxf((float)g_indeg[n], 1.f);
    float dd = fmaxf((float)g_outdeg[n], 1.f);
    float* x = &g_X10[n * 10];
    x[4] = g_acc[OFF_F2 + 2 * n] / di;  x[5] = g_acc[OFF_F2 + 2 * n + 1] / di;
    x[8] = g_acc[OFF_R2 + 2 * n] / dd;  x[9] = g_acc[OFF_R2 + 2 * n + 1] / dd;
}

// ---------------- operand prep (fp16) ----------------
// A operand: g_Axh[n][k] = fp16([e0 | X10 | 0]); rows >= nnodes zero-padded.
__global__ void prepA_kernel(const float* __restrict__ ent, const float* __restrict__ nont,
                             int ntext, int nnodes) {
    long gid = (long)blockIdx.x * blockDim.x + threadIdx.x;
    if (gid >= (long)NNP * KP2) return;
    int n = (int)(gid / KP2), k = (int)(gid - (long)n * KP2);
    float v = 0.f;
    if (n < nnodes) {
        if (k < 256)       v = (n < ntext) ? ent[(size_t)n * 256 + k] : nont[k];
        else if (k < 266)  v = g_X10[n * 10 + (k - 256)];
    }
    g_Axh[gid] = __float2half_rn(v);
}

// B operand (TRANSPOSED [n][k]) + relation-block weights.
// triple cols: [q:0-255 | h_e[h]:256-521 | h_r:522-777 | h_e[t]:778-1043]
// g_Bh[c][r]: tbl=c/1280 picks h(256)/t(778) base col; rows 256..265 = X10 block; 266.. = 0
__global__ void prepB_kernel() {
    int gid = blockIdx.x * blockDim.x + threadIdx.x;
    if (gid < CDIM * KP2) {
        int c = gid / KP2, r = gid - c * KP2;
        int tbl = c / 1280, cc = c % 1280;
        int s = cc / 256, k = cc % 256;
        int basecol = tbl ? 778 : 256;
        float v = 0.f;
        if (r < 266) v = g_W1[(size_t)s * W1SZ + k * 1044 + basecol + r];
        g_Bh[gid] = __float2half_rn(v);
    } else if (gid < CDIM * KP2 + 256 * HIDD) {
        int idx = gid - CDIM * KP2;
        int j = idx / HIDD, cc = idx % HIDD;
        int s = cc / 256, k = cc % 256;
        g_BR[j * HIDD + cc] = g_W1[(size_t)s * W1SZ + k * 1044 + 522 + j];
    }
}

__global__ void qb_kernel(const float* __restrict__ q) {
    int cc = blockIdx.x * blockDim.x + threadIdx.x;
    if (cc >= HIDD) return;
    int s = cc / 256, k = cc % 256;
    const float* w = &g_W1[(size_t)s * W1SZ + k * 1044];
    float sum = 0.f;
    for (int j = 0; j < 256; j++) sum += q[j] * w[j];
    g_qb[cc] = sum + g_b1s[cc];
}

__global__ void rproj_kernel(const float* __restrict__ rel, int nrel) {
    int gid = blockIdx.x * blockDim.x + threadIdx.x;
    if (gid >= nrel * HIDD) return;
    int r = gid / HIDD, cc = gid % HIDD;
    const float* rr = &rel[r * 256];
    float sum = 0.f;
    for (int j = 0; j < 256; j++) sum += rr[j] * g_BR[j * HIDD + cc];
    g_Rp[r * HIDD + cc] = __float2half_rn(sum + g_qb[cc]);   // fold qproj+b1 here (fp16 store)
}

// ---------------- main GEMM (fp16 tensor cores m16n8k16, fp32 accum, fp16 out) ----------------
// T[NNP, 2560] = g_Axh[NNP, 288] @ g_Bh[2560, 288]^T
// 128x128 block tile, BK=32, 8 warps (2x4), warp tile 64x32.
// smem word stride 20 (= 32 halves data + 8 halves pad): conflict-free for frag loads.
#define SM_STRIDE 20            // 32-bit words per row (A: [m][k], B: [n][k])

__device__ __forceinline__ void mma_f16(float c[4], uint32_t a0, uint32_t a1, uint32_t a2, uint32_t a3,
                                        uint32_t b0, uint32_t b1) {
    asm volatile(
        "mma.sync.aligned.m16n8k16.row.col.f32.f16.f16.f32 "
        "{%0,%1,%2,%3}, {%4,%5,%6,%7}, {%8,%9}, {%0,%1,%2,%3};"
        : "+f"(c[0]), "+f"(c[1]), "+f"(c[2]), "+f"(c[3])
        : "r"(a0), "r"(a1), "r"(a2), "r"(a3), "r"(b0), "r"(b1));
}

__global__ void __launch_bounds__(256, 2)
gemm_tc_kernel(int nnodes) {
    __shared__ __align__(16) uint32_t As[2][128 * SM_STRIDE];   // [m][k] f16x2 words
    __shared__ __align__(16) uint32_t Bs[2][128 * SM_STRIDE];   // [n][k] f16x2 words

    const int tid  = threadIdx.x;
    const int lane = tid & 31;
    const int warp = tid >> 5;
    const int wm = warp >> 2;          // 0..1
    const int wn = warp & 3;           // 0..3
    const int g  = lane >> 2;          // groupID 0..7
    const int t4 = lane & 3;           // threadID_in_group 0..3
    const int m0 = blockIdx.y * 128;
    const int n0 = blockIdx.x * 128;

    float c[4][4][4];
#pragma unroll
    for (int mt = 0; mt < 4; mt++)
#pragma unroll
        for (int nt = 0; nt < 4; nt++)
#pragma unroll
            for (int i = 0; i < 4; i++) c[mt][nt][i] = 0.f;

    // tile load mapping: 128 rows x 32 halves = 512 uint4; thread handles idx = tid, tid+256
    // row = idx>>2, kq = (idx&3) (uint4 = 8 halves = 4 words)
    uint4 aS[2], bS[2];
    const int ldRow[2] = { (tid + 0) >> 2, (tid + 256) >> 2 };
    const int ldKq[2]  = { (tid + 0) & 3, (tid + 256) & 3 };

    auto load_tile = [&](int k0) {
#pragma unroll
        for (int i = 0; i < 2; i++) {
            aS[i] = *(const uint4*)(g_Axh + (size_t)(m0 + ldRow[i]) * KP2 + k0 + ldKq[i] * 8);
            bS[i] = *(const uint4*)(g_Bh  + (size_t)(n0 + ldRow[i]) * KP2 + k0 + ldKq[i] * 8);
        }
    };
    auto store_tile = [&](int buf) {
#pragma unroll
        for (int i = 0; i < 2; i++) {
            *(uint4*)(As[buf] + ldRow[i] * SM_STRIDE + ldKq[i] * 4) = aS[i];
            *(uint4*)(Bs[buf] + ldRow[i] * SM_STRIDE + ldKq[i] * 4) = bS[i];
        }
    };

    load_tile(0);
    store_tile(0);
    __syncthreads();

    const int NIT = KP2 / 32;   // 9
    for (int it = 0; it < NIT; it++) {
        int buf = it & 1;
        if (it + 1 < NIT) load_tile((it + 1) * 32);

        const uint32_t* A_ = As[buf];
        const uint32_t* B_ = Bs[buf];
#pragma unroll
        for (int kk = 0; kk < 2; kk++) {        // two k16 steps within BK=32
            int kw = kk * 8;                    // word offset
            uint32_t af[4][4];
#pragma unroll
            for (int mt = 0; mt < 4; mt++) {
                int r0 = wm * 64 + mt * 16 + g;
                af[mt][0] = A_[r0 * SM_STRIDE + kw + t4];
                af[mt][1] = A_[(r0 + 8) * SM_STRIDE + kw + t4];
                af[mt][2] = A_[r0 * SM_STRIDE + kw + 4 + t4];
                af[mt][3] = A_[(r0 + 8) * SM_STRIDE + kw + 4 + t4];
            }
            uint32_t bf[4][2];
#pragma unroll
            for (int nt = 0; nt < 4; nt++) {
                int nb = wn * 32 + nt * 8 + g;
                bf[nt][0] = B_[nb * SM_STRIDE + kw + t4];
                bf[nt][1] = B_[nb * SM_STRIDE + kw + 4 + t4];
            }
#pragma unroll
            for (int mt = 0; mt < 4; mt++)
#pragma unroll
                for (int nt = 0; nt < 4; nt++)
                    mma_f16(c[mt][nt], af[mt][0], af[mt][1], af[mt][2], af[mt][3],
                            bf[nt][0], bf[nt][1]);
        }

        if (it + 1 < NIT) store_tile(buf ^ 1);
        __syncthreads();
    }

    // store C (fp16) to g_Th
#pragma unroll
    for (int mt = 0; mt < 4; mt++) {
        int r0 = m0 + wm * 64 + mt * 16 + g;
        int r1 = r0 + 8;
#pragma unroll
        for (int nt = 0; nt < 4; nt++) {
            int cb = n0 + wn * 32 + nt * 8 + 2 * t4;
            if (r0 < nnodes)
                *(__half2*)(g_Th + (size_t)r0 * CDIM + cb) =
                    __floats2half2_rn(c[mt][nt][0], c[mt][nt][1]);
            if (r1 < nnodes)
                *(__half2*)(g_Th + (size_t)r1 * CDIM + cb) =
                    __floats2half2_rn(c[mt][nt][2], c[mt][nt][3]);
        }
    }
}

// ---------------- edge phase: out[e] = mean_s( relu(pre) . w2_s + b2_s ) ----------------
__global__ void __launch_bounds__(256)
edge_kernel(const void* __restrict__ hid, const void* __restrict__ rid,
            const void* __restrict__ tidp, float* __restrict__ out, int E) {
    __shared__ float sw2[HIDD];
    for (int i = threadIdx.x; i < HIDD; i += blockDim.x) sw2[i] = g_w2s[i];
    __syncthreads();
    int warp = threadIdx.x >> 5, lane = threadIdx.x & 31;
    int e = blockIdx.x * 8 + warp;
    if (e >= E) return;
    long h = fetch_id(hid, e);
    long t = fetch_id(tidp, e);
    long r = fetch_id(rid, e);
    const uint4* ph = (const uint4*)(g_Th + (size_t)h * CDIM);          // 160 x 8 halves
    const uint4* pt = (const uint4*)(g_Th + (size_t)t * CDIM + 1280);
    const uint4* pr = (const uint4*)(g_Rp + (size_t)r * HIDD);
    float acc = 0.f;
#pragma unroll
    for (int c = 0; c < 5; c++) {
        int idx = c * 32 + lane;          // uint4 index; element base = idx*8
        uint4 ua = ph[idx];
        uint4 ub = pt[idx];
        uint4 uq = pr[idx];
        const __half2* a2 = (const __half2*)&ua;
        const __half2* b2 = (const __half2*)&ub;
        const __half2* q2 = (const __half2*)&uq;
        const float4* w4 = (const float4*)&sw2[idx * 8];
        float4 w0 = w4[0], w1 = w4[1];
        float wv[8] = {w0.x, w0.y, w0.z, w0.w, w1.x, w1.y, w1.z, w1.w};
#pragma unroll
        for (int j = 0; j < 4; j++) {
            float2 fa = __half22float2(a2[j]);
            float2 fb = __half22float2(b2[j]);
            float2 fq = __half22float2(q2[j]);
            acc += fmaxf(fa.x + fb.x + fq.x, 0.f) * wv[2 * j];
            acc += fmaxf(fa.y + fb.y + fq.y, 0.f) * wv[2 * j + 1];
        }
    }
#pragma unroll
    for (int o = 16; o; o >>= 1) acc += __shfl_xor_sync(0xFFFFFFFFu, acc, o);
    if (lane == 0) out[e] = acc * 0.2f + g_b2mean;
}

// ---------------- host ----------------
extern "C" void kernel_launch(void* const* d_in, const int* in_sizes, int n_in,
                              void* d_out, int out_size) {
    int base = 0;
    if (n_in >= 17 && in_sizes[5] <= 16) base = 1;

    const void*  hid   = d_in[0];
    const void*  rid   = d_in[1];
    const void*  tidp  = d_in[2];
    const float* q     = (const float*)d_in[3];
    const float* ent   = (const float*)d_in[4];
    const float* rel   = (const float*)d_in[5 + base];
    const float* topic = (const float*)d_in[6 + base];
    const float* nont  = (const float*)d_in[7 + base];
    const float* w1mu  = (const float*)d_in[8 + base];
    const float* w1rho = (const float*)d_in[9 + base];
    const float* b1mu  = (const float*)d_in[10 + base];
    const float* b1rho = (const float*)d_in[11 + base];
    const float* w2mu  = (const float*)d_in[12 + base];
    const float* w2rho = (const float*)d_in[13 + base];
    const float* b2mu  = (const float*)d_in[14 + base];
    const float* b2rho = (const float*)d_in[15 + base];

    int E = in_sizes[0];
    int ntext = in_sizes[4] / 256;
    int nrel  = in_sizes[5 + base] / 256;
    int nnodes = NN;
    float* out = (float*)d_out;

    zero_kernel<<<(8 * NN + 255) / 256, 256>>>();
    detect_kernel<<<1, 1>>>((const unsigned*)hid);
    sample_w1_kernel<<<(5 * W1SZ + 255) / 256, 256>>>(w1mu, w1rho);
    sample_small_kernel<<<11, 256>>>(b1mu, b1rho, w2mu, w2rho, b2mu, b2rho);
    scat1_kernel<<<(E + 255) / 256, 256>>>(hid, tidp, topic, E);
    fin1_kernel<<<(NN + 255) / 256, 256>>>(topic);
    scat2_kernel<<<(E + 255) / 256, 256>>>(hid, tidp, E);
    fin2_kernel<<<(NN + 255) / 256, 256>>>();
    {
        long totA = (long)NNP * KP2;
        prepA_kernel<<<(int)((totA + 255) / 256), 256>>>(ent, nont, ntext, nnodes);
    }
    {
        int tot = CDIM * KP2 + 256 * HIDD;
        prepB_kernel<<<(tot + 255) / 256, 256>>>();
    }
    qb_kernel<<<(HIDD + 255) / 256, 256>>>(q);
    rproj_kernel<<<(nrel * HIDD + 255) / 256, 256>>>(rel, nrel);
    {
        dim3 grid(CDIM / 128, NNP / 128);   // x = n-tiles (20), y = m-tiles (782)
        gemm_tc_kernel<<<grid, 256>>>(nnodes);
    }
    edge_kernel<<<(E + 7) / 8, 256>>>(hid, rid, tidp, out, E);
}